// round 4
// baseline (speedup 1.0000x reference)
#include <cuda_runtime.h>
#include <math.h>
#include <stdint.h>

#define B_    32
#define L_    1024
#define CIN_  64
#define D_    512
#define DFF_  2048
#define NL_   3
#define TOPK_ 6
#define MROWS (B_*L_)   /* 32768 */

// ---------------- scratch (device globals; allocation-free) ----------------
__device__ float  g_h  [MROWS*D_];
__device__ float  g_h2 [MROWS*D_];
__device__ float  g_q  [MROWS*D_];
__device__ float  g_k  [MROWS*D_];
__device__ float  g_v  [MROWS*D_];
__device__ float  g_a  [MROWS*D_];
__device__ float  g_t  [MROWS*D_];
__device__ float  g_ffn[MROWS*DFF_];
__device__ float  g_xcat[MROWS*3*CIN_];
__device__ float2 g_Spart[B_*32*L_];
__device__ float  g_corr[B_*L_];
__device__ float  g_tcw [B_*TOPK_];
__device__ int    g_dly [B_*TOPK_];
__device__ float  g_cm  [B_*D_];
__device__ float  g_cb  [B_*CIN_];

// ---------------- complex helpers ----------------
__device__ __forceinline__ float2 cadd(float2 a, float2 b){ return make_float2(a.x+b.x, a.y+b.y); }
__device__ __forceinline__ float2 csub(float2 a, float2 b){ return make_float2(a.x-b.x, a.y-b.y); }
__device__ __forceinline__ float2 cmul(float2 a, float2 b){ return make_float2(a.x*b.x-a.y*b.y, a.x*b.y+a.y*b.x); }

// ---------------- circular-pad gather for token embedding ----------------
__global__ void xcat_kernel(const float* __restrict__ x, float* __restrict__ xc)
{
    int idx = blockIdx.x*blockDim.x + threadIdx.x;
    if (idx >= MROWS*192) return;
    int row = idx / 192, cc = idx % 192;
    int j = cc >> 6, c = cc & 63;
    int b = row >> 10, l = row & 1023;
    int ls = (l + j + 1023) & 1023;          // (l + j - 1) mod L
    xc[idx] = x[((((size_t)b)<<10) + ls)*64 + c];
}

// ---------------- fp32 SGEMM: C = A(MxK) * B(KxN) [+bias][gelu] ----------------
template<int GELU>
__global__ __launch_bounds__(256)
void sgemm_kernel(const float* __restrict__ A, const float* __restrict__ Bm,
                  const float* __restrict__ bias, float* __restrict__ C,
                  int M, int N, int K)
{
    __shared__ float As[16][128];
    __shared__ float Bs[16][128];
    int tid = threadIdx.x;
    int tx = tid & 15, ty = tid >> 4;
    int bx = blockIdx.x, by = blockIdx.y;

    int aRow = tid >> 2;
    int aCol = (tid & 3) << 2;
    int bRow = tid >> 5;
    int bCol = (tid & 31) << 2;

    const float* Ab = A + ((size_t)by * 128) * (size_t)K;

    float acc[8][8];
#pragma unroll
    for (int i = 0; i < 8; i++)
#pragma unroll
        for (int j = 0; j < 8; j++) acc[i][j] = 0.f;

    for (int k0 = 0; k0 < K; k0 += 16) {
#pragma unroll
        for (int i = 0; i < 2; i++) {
            float4 va = *(const float4*)(Ab + (size_t)(aRow + i*64)*K + k0 + aCol);
            As[aCol+0][aRow+i*64] = va.x;
            As[aCol+1][aRow+i*64] = va.y;
            As[aCol+2][aRow+i*64] = va.z;
            As[aCol+3][aRow+i*64] = va.w;
        }
#pragma unroll
        for (int i = 0; i < 2; i++) {
            int c = bx*128 + bCol;
            float4 vb = make_float4(0.f,0.f,0.f,0.f);
            if (c < N) vb = *(const float4*)(Bm + (size_t)(k0 + bRow + i*8)*N + c);
            *(float4*)&Bs[bRow+i*8][bCol] = vb;
        }
        __syncthreads();
#pragma unroll
        for (int kk = 0; kk < 16; kk++) {
            float ar[8], br[8];
            *(float4*)&ar[0] = *(const float4*)&As[kk][ty*8];
            *(float4*)&ar[4] = *(const float4*)&As[kk][ty*8+4];
            *(float4*)&br[0] = *(const float4*)&Bs[kk][tx*8];
            *(float4*)&br[4] = *(const float4*)&Bs[kk][tx*8+4];
#pragma unroll
            for (int i = 0; i < 8; i++)
#pragma unroll
                for (int j = 0; j < 8; j++)
                    acc[i][j] = fmaf(ar[i], br[j], acc[i][j]);
        }
        __syncthreads();
    }

#pragma unroll
    for (int i = 0; i < 8; i++) {
        int r = by*128 + ty*8 + i;
        float* crow = C + (size_t)r * (size_t)N;
#pragma unroll
        for (int jj = 0; jj < 8; jj += 4) {
            int c = bx*128 + tx*8 + jj;
            if (c < N) {
                float4 v;
                v.x = acc[i][jj+0]; v.y = acc[i][jj+1];
                v.z = acc[i][jj+2]; v.w = acc[i][jj+3];
                if (bias != nullptr) {
                    v.x += bias[c+0]; v.y += bias[c+1];
                    v.z += bias[c+2]; v.w += bias[c+3];
                }
                if (GELU) {
                    v.x = 0.5f*v.x*(1.f + erff(v.x*0.7071067811865475f));
                    v.y = 0.5f*v.y*(1.f + erff(v.y*0.7071067811865475f));
                    v.z = 0.5f*v.z*(1.f + erff(v.z*0.7071067811865475f));
                    v.w = 0.5f*v.w*(1.f + erff(v.w*0.7071067811865475f));
                }
                *(float4*)(crow + c) = v;
            }
        }
    }
}

// ---------------- length-1024 in-place radix-2 FFT (input bit-reversed) ----------------
__device__ void fft1024(float2* z, const float2* tw)
{
    int tid = threadIdx.x;   // blockDim == 256
    for (int half = 1; half < 1024; half <<= 1) {
        int step = 512 / half;
#pragma unroll 2
        for (int idx = tid; idx < 512; idx += 256) {
            int j = idx & (half - 1);
            int base = (idx & ~(half - 1)) << 1;
            float2 w = tw[j * step];
            float2 u = z[base + j];
            float2 t = cmul(w, z[base + j + half]);
            z[base + j]        = cadd(u, t);
            z[base + j + half] = csub(u, t);
        }
        __syncthreads();
    }
}

// S_partial[b,g,f] = sum over 16 channels of Q_d[f] * conj(K_d[f])
__global__ __launch_bounds__(256)
void corr_fft_kernel(const float* __restrict__ q, const float* __restrict__ k,
                     float2* __restrict__ Spart)
{
    __shared__ float2 z[1024];
    __shared__ float2 acc[1024];
    __shared__ float2 tw[512];
    int tid = threadIdx.x;
    int b = blockIdx.x, g = blockIdx.y;

    for (int i = tid; i < 512; i += 256) {
        float s, c;
        sincosf(-6.283185307179586f * (float)i / 1024.f, &s, &c);
        tw[i] = make_float2(c, s);
    }
    for (int i = tid; i < 1024; i += 256) acc[i] = make_float2(0.f, 0.f);
    __syncthreads();

    const float* qb = q + (((size_t)b) << 10) * 512;
    const float* kb = k + (((size_t)b) << 10) * 512;

    for (int dd = 0; dd < 16; dd++) {
        int d = (g << 4) + dd;
        for (int t = tid; t < 1024; t += 256) {
            int r = __brev((unsigned)t) >> 22;
            z[r] = make_float2(qb[(((size_t)t) << 9) + d], kb[(((size_t)t) << 9) + d]);
        }
        __syncthreads();
        fft1024(z, tw);
        for (int f = tid; f < 1024; f += 256) {
            float2 Zf = z[f];
            float2 Zm = z[(1024 - f) & 1023];
            float Qx = 0.5f*(Zf.x + Zm.x), Qy = 0.5f*(Zf.y - Zm.y);
            float Kx = 0.5f*(Zf.y + Zm.y), Ky = 0.5f*(Zm.x - Zf.x);
            // P = Q * conj(K)
            float2 P = make_float2(Qx*Kx + Qy*Ky, Qy*Kx - Qx*Ky);
            acc[f] = cadd(acc[f], P);
        }
        __syncthreads();
    }
    float2* outp = Spart + ((((size_t)b) << 5) + g) * 1024;
    for (int f = tid; f < 1024; f += 256) outp[f] = acc[f];
}

// mean_corr[b,tau] = Re(ifft(sum_g Spart))[tau] / 512
__global__ __launch_bounds__(256)
void corr_ifft_kernel(const float2* __restrict__ Spart, float* __restrict__ corr)
{
    __shared__ float2 z[1024];
    __shared__ float2 tw[512];
    int tid = threadIdx.x;
    int b = blockIdx.x;

    for (int i = tid; i < 512; i += 256) {
        float s, c;
        sincosf(6.283185307179586f * (float)i / 1024.f, &s, &c);
        tw[i] = make_float2(c, s);
    }
    __syncthreads();
    for (int t = tid; t < 1024; t += 256) {
        float2 s = make_float2(0.f, 0.f);
        const float2* sp = Spart + ((((size_t)b) << 5) * 1024) + t;
        for (int g2 = 0; g2 < 32; g2++) s = cadd(s, sp[(size_t)g2 << 10]);
        z[__brev((unsigned)t) >> 22] = s;
    }
    __syncthreads();
    fft1024(z, tw);
    const float scale = 1.f / (1024.f * 512.f);
    for (int t = tid; t < 1024; t += 256)
        corr[(b << 10) + t] = z[t].x * scale;
}

// top-6 + softmax per batch
__global__ __launch_bounds__(256)
void topk_kernel(const float* __restrict__ corr, float* __restrict__ tcw, int* __restrict__ dly)
{
    int b = blockIdx.x, t = threadIdx.x;
    __shared__ float vals[1024];
    __shared__ float rv[256];
    __shared__ int   ri[256];
    __shared__ float wv[TOPK_];
    __shared__ int   wi[TOPK_];
    for (int i = t; i < 1024; i += 256) vals[i] = corr[(b << 10) + i];
    __syncthreads();
    for (int kk = 0; kk < TOPK_; kk++) {
        float bm = -INFINITY; int bi = 0x7fffffff;
        for (int i = t; i < 1024; i += 256) {
            float v = vals[i];
            if (v > bm || (v == bm && i < bi)) { bm = v; bi = i; }
        }
        rv[t] = bm; ri[t] = bi;
        __syncthreads();
        for (int s = 128; s > 0; s >>= 1) {
            if (t < s) {
                if (rv[t+s] > rv[t] || (rv[t+s] == rv[t] && ri[t+s] < ri[t])) {
                    rv[t] = rv[t+s]; ri[t] = ri[t+s];
                }
            }
            __syncthreads();
        }
        if (t == 0) { wv[kk] = rv[0]; wi[kk] = ri[0]; vals[ri[0]] = -INFINITY; }
        __syncthreads();
    }
    if (t == 0) {
        float m = wv[0];
        for (int kk = 1; kk < TOPK_; kk++) m = fmaxf(m, wv[kk]);
        float e[TOPK_], s = 0.f;
        for (int kk = 0; kk < TOPK_; kk++) { e[kk] = expf(wv[kk] - m); s += e[kk]; }
        float inv = 1.f / s;
        for (int kk = 0; kk < TOPK_; kk++) {
            tcw[b*TOPK_ + kk] = e[kk] * inv;
            dly[b*TOPK_ + kk] = wi[kk];
        }
    }
}

// a[b,l,:] = sum_k tc_k * v[b,(l+delay_k)%L,:]
__global__ __launch_bounds__(128)
void agg_kernel(const float* __restrict__ v, const float* __restrict__ tcw,
                const int* __restrict__ dly, float* __restrict__ outp)
{
    int bl = blockIdx.x;
    int b = bl >> 10, l = bl & 1023;
    __shared__ float w[TOPK_];
    __shared__ int   dd[TOPK_];
    if (threadIdx.x < TOPK_) {
        w[threadIdx.x]  = tcw[b*TOPK_ + threadIdx.x];
        dd[threadIdx.x] = dly[b*TOPK_ + threadIdx.x];
    }
    __syncthreads();
    int c = threadIdx.x << 2;
    float4 acc = make_float4(0.f, 0.f, 0.f, 0.f);
#pragma unroll
    for (int kk = 0; kk < TOPK_; kk++) {
        int row = (l + dd[kk]) & 1023;
        float4 vv = *(const float4*)(v + (((((size_t)b) << 10) + row) << 9) + c);
        acc.x = fmaf(w[kk], vv.x, acc.x);
        acc.y = fmaf(w[kk], vv.y, acc.y);
        acc.z = fmaf(w[kk], vv.z, acc.z);
        acc.w = fmaf(w[kk], vv.w, acc.w);
    }
    *(float4*)(outp + (((size_t)bl) << 9) + c) = acc;
}

// out = s - movavg25(s), s = in1 + in2, edge-replicated (clamped) window
__global__ __launch_bounds__(256)
void decomp_kernel(const float* __restrict__ in1, const float* __restrict__ in2,
                   float* __restrict__ outp)
{
    __shared__ float s[152][64];
    int b = blockIdx.x, lt = blockIdx.y, dt = blockIdx.z;
    int l0 = lt << 7, d0 = dt << 6;
    int tid = threadIdx.x;
    for (int i = tid; i < 152*64; i += 256) {
        int r = i >> 6, d = i & 63;
        int l = l0 - 12 + r;
        l = l < 0 ? 0 : (l > 1023 ? 1023 : l);
        size_t gi = (((((size_t)b) << 10) + l) << 9) + d0 + d;
        s[r][d] = in1[gi] + in2[gi];
    }
    __syncthreads();
    int d = tid & 63, ch = tid >> 6;
    int lb = ch << 5;
    float sum = 0.f;
#pragma unroll
    for (int j = 0; j < 25; j++) sum += s[lb + j][d];
    for (int i = 0; i < 32; i++) {
        size_t gi = (((((size_t)b) << 10) + (l0 + lb + i)) << 9) + d0 + d;
        outp[gi] = s[lb + 12 + i][d] - sum * (1.f/25.f);
        if (i != 31) sum += s[lb + 25 + i][d] - s[lb + i][d];
    }
}

// layernorm (over D) with gamma/beta
__global__ __launch_bounds__(128)
void ln_kernel(const float* __restrict__ h, const float* __restrict__ gam,
               const float* __restrict__ bet, float* __restrict__ hn)
{
    int row = blockIdx.x;
    int t = threadIdx.x;
    const float4 x = *(const float4*)(h + (((size_t)row) << 9) + (t << 2));
    float s1 = x.x + x.y + x.z + x.w;
    float s2 = x.x*x.x + x.y*x.y + x.z*x.z + x.w*x.w;
#pragma unroll
    for (int o = 16; o > 0; o >>= 1) {
        s1 += __shfl_xor_sync(0xffffffffu, s1, o);
        s2 += __shfl_xor_sync(0xffffffffu, s2, o);
    }
    __shared__ float a1[4], a2[4];
    if ((t & 31) == 0) { a1[t >> 5] = s1; a2[t >> 5] = s2; }
    __syncthreads();
    s1 = a1[0] + a1[1] + a1[2] + a1[3];
    s2 = a2[0] + a2[1] + a2[2] + a2[3];
    float mu  = s1 * (1.f/512.f);
    float var = s2 * (1.f/512.f) - mu*mu;
    float rs  = rsqrtf(var + 1e-5f);
    int c = t << 2;
    float4 o4;
    o4.x = (x.x - mu)*rs*gam[c+0] + bet[c+0];
    o4.y = (x.y - mu)*rs*gam[c+1] + bet[c+1];
    o4.z = (x.z - mu)*rs*gam[c+2] + bet[c+2];
    o4.w = (x.w - mu)*rs*gam[c+3] + bet[c+3];
    *(float4*)(hn + (((size_t)row) << 9) + c) = o4;
}

// per-(b,d) mean over L of hn
__global__ __launch_bounds__(128)
void colmean_kernel(const float* __restrict__ hn, float* __restrict__ cm)
{
    int b = blockIdx.x;
    int d = blockIdx.y * 128 + threadIdx.x;
    float s = 0.f;
    const float* p = hn + ((((size_t)b) << 10) << 9) + d;
    for (int l = 0; l < 1024; l++) s += p[((size_t)l) << 9];
    cm[(b << 9) + d] = s * (1.f/1024.f);
}

// cb[b,n] = colmean[b,:] @ proj_w[:,n]
__global__ __launch_bounds__(64)
void cbias_kernel(const float* __restrict__ cm, const float* __restrict__ pw,
                  float* __restrict__ cb)
{
    int b = blockIdx.x, n = threadIdx.x;
    float s = 0.f;
    for (int d2 = 0; d2 < 512; d2++) s = fmaf(cm[(b << 9) + d2], pw[d2*64 + n], s);
    cb[(b << 6) + n] = s;
}

// out[b,l,n] -= cb[b,n]
__global__ void sub_kernel(float* __restrict__ outp, const float* __restrict__ cb)
{
    int i = blockIdx.x * blockDim.x + threadIdx.x;
    if (i >= MROWS*64) return;
    outp[i] -= cb[((i >> 16) << 6) + (i & 63)];
}

// ---------------- host launcher ----------------
extern "C" void kernel_launch(void* const* d_in, const int* in_sizes, int n_in,
                              void* d_out, int out_size)
{
    const float* x       = (const float*)d_in[0];
    const float* embed_w = (const float*)d_in[1];
    const float* wq = (const float*)d_in[2];  const float* bq = (const float*)d_in[3];
    const float* wk = (const float*)d_in[4];  const float* bk = (const float*)d_in[5];
    const float* wv = (const float*)d_in[6];  const float* bv = (const float*)d_in[7];
    const float* wo = (const float*)d_in[8];  const float* bo = (const float*)d_in[9];
    const float* w1 = (const float*)d_in[10]; const float* w2 = (const float*)d_in[11];
    const float* ln_g = (const float*)d_in[12]; const float* ln_b = (const float*)d_in[13];
    const float* pw = (const float*)d_in[14]; const float* pb = (const float*)d_in[15];
    float* outp = (float*)d_out;
    (void)in_sizes; (void)n_in; (void)out_size;

    float *h, *h2, *q, *k, *v, *a, *t, *ffn, *xc, *corr, *tcw, *cm, *cb;
    float2* sp; int* dly;
    cudaGetSymbolAddress((void**)&h,   g_h);
    cudaGetSymbolAddress((void**)&h2,  g_h2);
    cudaGetSymbolAddress((void**)&q,   g_q);
    cudaGetSymbolAddress((void**)&k,   g_k);
    cudaGetSymbolAddress((void**)&v,   g_v);
    cudaGetSymbolAddress((void**)&a,   g_a);
    cudaGetSymbolAddress((void**)&t,   g_t);
    cudaGetSymbolAddress((void**)&ffn, g_ffn);
    cudaGetSymbolAddress((void**)&xc,  g_xcat);
    cudaGetSymbolAddress((void**)&sp,  g_Spart);
    cudaGetSymbolAddress((void**)&corr,g_corr);
    cudaGetSymbolAddress((void**)&tcw, g_tcw);
    cudaGetSymbolAddress((void**)&dly, g_dly);
    cudaGetSymbolAddress((void**)&cm,  g_cm);
    cudaGetSymbolAddress((void**)&cb,  g_cb);

    dim3 gN512(4, MROWS/128);
    dim3 gN2048(16, MROWS/128);
    dim3 gN64(1, MROWS/128);

    // token embedding (circular conv1d k=3 as gather + GEMM)
    xcat_kernel<<<(MROWS*192 + 255)/256, 256>>>(x, xc);
    sgemm_kernel<0><<<gN512, 256>>>(xc, embed_w, nullptr, h, MROWS, 512, 192);

    for (int l = 0; l < NL_; l++) {
        const float* wql = wq + (size_t)l*D_*D_;  const float* bql = bq + l*D_;
        const float* wkl = wk + (size_t)l*D_*D_;  const float* bkl = bk + l*D_;
        const float* wvl = wv + (size_t)l*D_*D_;  const float* bvl = bv + l*D_;
        const float* wol = wo + (size_t)l*D_*D_;  const float* bol = bo + l*D_;
        const float* w1l = w1 + (size_t)l*D_*DFF_;
        const float* w2l = w2 + (size_t)l*DFF_*D_;

        sgemm_kernel<0><<<gN512, 256>>>(h, wql, bql, q, MROWS, 512, 512);
        sgemm_kernel<0><<<gN512, 256>>>(h, wkl, bkl, k, MROWS, 512, 512);
        sgemm_kernel<0><<<gN512, 256>>>(h, wvl, bvl, v, MROWS, 512, 512);

        corr_fft_kernel <<<dim3(B_, 32), 256>>>(q, k, sp);
        corr_ifft_kernel<<<B_, 256>>>(sp, corr);
        topk_kernel     <<<B_, 256>>>(corr, tcw, dly);
        agg_kernel      <<<MROWS, 128>>>(v, tcw, dly, a);

        sgemm_kernel<0><<<gN512, 256>>>(a, wol, bol, t, MROWS, 512, 512);
        decomp_kernel<<<dim3(B_, 8, 8), 256>>>(h, t, h2);

        sgemm_kernel<1><<<gN2048, 256>>>(h2, w1l, nullptr, ffn, MROWS, 2048, 512);
        sgemm_kernel<0><<<gN512, 256>>>(ffn, w2l, nullptr, t, MROWS, 512, 2048);
        decomp_kernel<<<dim3(B_, 8, 8), 256>>>(h2, t, h);
    }

    // final my_Layernorm + time-mean subtraction + projection
    ln_kernel<<<MROWS, 128>>>(h, ln_g, ln_b, q);            // hn -> g_q
    colmean_kernel<<<dim3(B_, 4), 128>>>(q, cm);
    cbias_kernel<<<B_, 64>>>(cm, pw, cb);
    sgemm_kernel<0><<<gN64, 256>>>(q, pw, pb, outp, MROWS, 64, 512);
    sub_kernel<<<(MROWS*64 + 255)/256, 256>>>(outp, cb);
}

// round 5
// speedup vs baseline: 1.0029x; 1.0029x over previous
#include <cuda_runtime.h>
#include <math.h>
#include <stdint.h>

#define B_    32
#define L_    1024
#define CIN_  64
#define D_    512
#define DFF_  2048
#define NL_   3
#define TOPK_ 6
#define MROWS (B_*L_)   /* 32768 */

// ---------------- scratch (device globals; allocation-free) ----------------
__device__ float  g_h  [MROWS*D_];
__device__ float  g_h2 [MROWS*D_];
__device__ float  g_q  [MROWS*D_];
__device__ float  g_k  [MROWS*D_];
__device__ float  g_v  [MROWS*D_];
__device__ float  g_a  [MROWS*D_];
__device__ float  g_t  [MROWS*D_];
__device__ float  g_ffn[MROWS*DFF_];
__device__ float  g_xcat[MROWS*3*CIN_];
__device__ float2 g_Spart[B_*32*L_];
__device__ float  g_corr[B_*L_];
__device__ float  g_tcw [B_*TOPK_];
__device__ int    g_dly [B_*TOPK_];
__device__ float  g_cm  [B_*D_];
__device__ float  g_cb  [B_*CIN_];

// ---------------- complex helpers ----------------
__device__ __forceinline__ float2 cadd(float2 a, float2 b){ return make_float2(a.x+b.x, a.y+b.y); }
__device__ __forceinline__ float2 csub(float2 a, float2 b){ return make_float2(a.x-b.x, a.y-b.y); }
__device__ __forceinline__ float2 cmul(float2 a, float2 b){ return make_float2(a.x*b.x-a.y*b.y, a.x*b.y+a.y*b.x); }

// ---------------- circular-pad gather for token embedding ----------------
__global__ void xcat_kernel(const float* __restrict__ x, float* __restrict__ xc)
{
    int idx = blockIdx.x*blockDim.x + threadIdx.x;
    if (idx >= MROWS*192) return;
    int row = idx / 192, cc = idx % 192;
    int j = cc >> 6, c = cc & 63;
    int b = row >> 10, l = row & 1023;
    int ls = (l + j + 1023) & 1023;          // (l + j - 1) mod L
    xc[idx] = x[((((size_t)b)<<10) + ls)*64 + c];
}

// ---------------- fp32 SGEMM: C = A(MxK) * B(KxN) [+bias][gelu] ----------------
template<int GELU>
__global__ __launch_bounds__(256)
void sgemm_kernel(const float* __restrict__ A, const float* __restrict__ Bm,
                  const float* __restrict__ bias, float* __restrict__ C,
                  int M, int N, int K)
{
    __shared__ float As[16][128];
    __shared__ float Bs[16][128];
    int tid = threadIdx.x;
    int tx = tid & 15, ty = tid >> 4;
    int bx = blockIdx.x, by = blockIdx.y;

    int aRow = tid >> 2;
    int aCol = (tid & 3) << 2;
    int bRow = tid >> 5;
    int bCol = (tid & 31) << 2;

    const float* Ab = A + ((size_t)by * 128) * (size_t)K;

    float acc[8][8];
#pragma unroll
    for (int i = 0; i < 8; i++)
#pragma unroll
        for (int j = 0; j < 8; j++) acc[i][j] = 0.f;

    for (int k0 = 0; k0 < K; k0 += 16) {
#pragma unroll
        for (int i = 0; i < 2; i++) {
            float4 va = *(const float4*)(Ab + (size_t)(aRow + i*64)*K + k0 + aCol);
            As[aCol+0][aRow+i*64] = va.x;
            As[aCol+1][aRow+i*64] = va.y;
            As[aCol+2][aRow+i*64] = va.z;
            As[aCol+3][aRow+i*64] = va.w;
        }
#pragma unroll
        for (int i = 0; i < 2; i++) {
            int c = bx*128 + bCol;
            float4 vb = make_float4(0.f,0.f,0.f,0.f);
            if (c < N) vb = *(const float4*)(Bm + (size_t)(k0 + bRow + i*8)*N + c);
            *(float4*)&Bs[bRow+i*8][bCol] = vb;
        }
        __syncthreads();
#pragma unroll
        for (int kk = 0; kk < 16; kk++) {
            float ar[8], br[8];
            *(float4*)&ar[0] = *(const float4*)&As[kk][ty*8];
            *(float4*)&ar[4] = *(const float4*)&As[kk][ty*8+4];
            *(float4*)&br[0] = *(const float4*)&Bs[kk][tx*8];
            *(float4*)&br[4] = *(const float4*)&Bs[kk][tx*8+4];
#pragma unroll
            for (int i = 0; i < 8; i++)
#pragma unroll
                for (int j = 0; j < 8; j++)
                    acc[i][j] = fmaf(ar[i], br[j], acc[i][j]);
        }
        __syncthreads();
    }

#pragma unroll
    for (int i = 0; i < 8; i++) {
        int r = by*128 + ty*8 + i;
        float* crow = C + (size_t)r * (size_t)N;
#pragma unroll
        for (int jj = 0; jj < 8; jj += 4) {
            int c = bx*128 + tx*8 + jj;
            if (c < N) {
                float4 v;
                v.x = acc[i][jj+0]; v.y = acc[i][jj+1];
                v.z = acc[i][jj+2]; v.w = acc[i][jj+3];
                if (bias != nullptr) {
                    v.x += bias[c+0]; v.y += bias[c+1];
                    v.z += bias[c+2]; v.w += bias[c+3];
                }
                if (GELU) {
                    v.x = 0.5f*v.x*(1.f + erff(v.x*0.7071067811865475f));
                    v.y = 0.5f*v.y*(1.f + erff(v.y*0.7071067811865475f));
                    v.z = 0.5f*v.z*(1.f + erff(v.z*0.7071067811865475f));
                    v.w = 0.5f*v.w*(1.f + erff(v.w*0.7071067811865475f));
                }
                *(float4*)(crow + c) = v;
            }
        }
    }
}

// ---------------- length-1024 in-place radix-2 FFT (input bit-reversed) ----------------
__device__ void fft1024(float2* z, const float2* tw)
{
    int tid = threadIdx.x;   // blockDim == 256
    for (int half = 1; half < 1024; half <<= 1) {
        int step = 512 / half;
#pragma unroll 2
        for (int idx = tid; idx < 512; idx += 256) {
            int j = idx & (half - 1);
            int base = (idx & ~(half - 1)) << 1;
            float2 w = tw[j * step];
            float2 u = z[base + j];
            float2 t = cmul(w, z[base + j + half]);
            z[base + j]        = cadd(u, t);
            z[base + j + half] = csub(u, t);
        }
        __syncthreads();
    }
}

// S_partial[b,g,f] = sum over 16 channels of Q_d[f] * conj(K_d[f])
__global__ __launch_bounds__(256)
void corr_fft_kernel(const float* __restrict__ q, const float* __restrict__ k,
                     float2* __restrict__ Spart)
{
    __shared__ float2 z[1024];
    __shared__ float2 acc[1024];
    __shared__ float2 tw[512];
    int tid = threadIdx.x;
    int b = blockIdx.x, g = blockIdx.y;

    for (int i = tid; i < 512; i += 256) {
        float s, c;
        sincosf(-6.283185307179586f * (float)i / 1024.f, &s, &c);
        tw[i] = make_float2(c, s);
    }
    for (int i = tid; i < 1024; i += 256) acc[i] = make_float2(0.f, 0.f);
    __syncthreads();

    const float* qb = q + (((size_t)b) << 10) * 512;
    const float* kb = k + (((size_t)b) << 10) * 512;

    for (int dd = 0; dd < 16; dd++) {
        int d = (g << 4) + dd;
        for (int t = tid; t < 1024; t += 256) {
            int r = __brev((unsigned)t) >> 22;
            z[r] = make_float2(qb[(((size_t)t) << 9) + d], kb[(((size_t)t) << 9) + d]);
        }
        __syncthreads();
        fft1024(z, tw);
        for (int f = tid; f < 1024; f += 256) {
            float2 Zf = z[f];
            float2 Zm = z[(1024 - f) & 1023];
            float Qx = 0.5f*(Zf.x + Zm.x), Qy = 0.5f*(Zf.y - Zm.y);
            float Kx = 0.5f*(Zf.y + Zm.y), Ky = 0.5f*(Zm.x - Zf.x);
            // P = Q * conj(K)
            float2 P = make_float2(Qx*Kx + Qy*Ky, Qy*Kx - Qx*Ky);
            acc[f] = cadd(acc[f], P);
        }
        __syncthreads();
    }
    float2* outp = Spart + ((((size_t)b) << 5) + g) * 1024;
    for (int f = tid; f < 1024; f += 256) outp[f] = acc[f];
}

// mean_corr[b,tau] = Re(ifft(sum_g Spart))[tau] / 512
__global__ __launch_bounds__(256)
void corr_ifft_kernel(const float2* __restrict__ Spart, float* __restrict__ corr)
{
    __shared__ float2 z[1024];
    __shared__ float2 tw[512];
    int tid = threadIdx.x;
    int b = blockIdx.x;

    for (int i = tid; i < 512; i += 256) {
        float s, c;
        sincosf(6.283185307179586f * (float)i / 1024.f, &s, &c);
        tw[i] = make_float2(c, s);
    }
    __syncthreads();
    for (int t = tid; t < 1024; t += 256) {
        float2 s = make_float2(0.f, 0.f);
        const float2* sp = Spart + ((((size_t)b) << 5) * 1024) + t;
        for (int g2 = 0; g2 < 32; g2++) s = cadd(s, sp[(size_t)g2 << 10]);
        z[__brev((unsigned)t) >> 22] = s;
    }
    __syncthreads();
    fft1024(z, tw);
    const float scale = 1.f / (1024.f * 512.f);
    for (int t = tid; t < 1024; t += 256)
        corr[(b << 10) + t] = z[t].x * scale;
}

// top-6 + softmax per batch
__global__ __launch_bounds__(256)
void topk_kernel(const float* __restrict__ corr, float* __restrict__ tcw, int* __restrict__ dly)
{
    int b = blockIdx.x, t = threadIdx.x;
    __shared__ float vals[1024];
    __shared__ float rv[256];
    __shared__ int   ri[256];
    __shared__ float wv[TOPK_];
    __shared__ int   wi[TOPK_];
    for (int i = t; i < 1024; i += 256) vals[i] = corr[(b << 10) + i];
    __syncthreads();
    for (int kk = 0; kk < TOPK_; kk++) {
        float bm = -INFINITY; int bi = 0x7fffffff;
        for (int i = t; i < 1024; i += 256) {
            float v = vals[i];
            if (v > bm || (v == bm && i < bi)) { bm = v; bi = i; }
        }
        rv[t] = bm; ri[t] = bi;
        __syncthreads();
        for (int s = 128; s > 0; s >>= 1) {
            if (t < s) {
                if (rv[t+s] > rv[t] || (rv[t+s] == rv[t] && ri[t+s] < ri[t])) {
                    rv[t] = rv[t+s]; ri[t] = ri[t+s];
                }
            }
            __syncthreads();
        }
        if (t == 0) { wv[kk] = rv[0]; wi[kk] = ri[0]; vals[ri[0]] = -INFINITY; }
        __syncthreads();
    }
    if (t == 0) {
        float m = wv[0];
        for (int kk = 1; kk < TOPK_; kk++) m = fmaxf(m, wv[kk]);
        float e[TOPK_], s = 0.f;
        for (int kk = 0; kk < TOPK_; kk++) { e[kk] = expf(wv[kk] - m); s += e[kk]; }
        float inv = 1.f / s;
        for (int kk = 0; kk < TOPK_; kk++) {
            tcw[b*TOPK_ + kk] = e[kk] * inv;
            dly[b*TOPK_ + kk] = wi[kk];
        }
    }
}

// a[b,l,:] = sum_k tc_k * v[b,(l+delay_k)%L,:]
__global__ __launch_bounds__(128)
void agg_kernel(const float* __restrict__ v, const float* __restrict__ tcw,
                const int* __restrict__ dly, float* __restrict__ outp)
{
    int bl = blockIdx.x;
    int b = bl >> 10, l = bl & 1023;
    __shared__ float w[TOPK_];
    __shared__ int   dd[TOPK_];
    if (threadIdx.x < TOPK_) {
        w[threadIdx.x]  = tcw[b*TOPK_ + threadIdx.x];
        dd[threadIdx.x] = dly[b*TOPK_ + threadIdx.x];
    }
    __syncthreads();
    int c = threadIdx.x << 2;
    float4 acc = make_float4(0.f, 0.f, 0.f, 0.f);
#pragma unroll
    for (int kk = 0; kk < TOPK_; kk++) {
        int row = (l + dd[kk]) & 1023;
        float4 vv = *(const float4*)(v + (((((size_t)b) << 10) + row) << 9) + c);
        acc.x = fmaf(w[kk], vv.x, acc.x);
        acc.y = fmaf(w[kk], vv.y, acc.y);
        acc.z = fmaf(w[kk], vv.z, acc.z);
        acc.w = fmaf(w[kk], vv.w, acc.w);
    }
    *(float4*)(outp + (((size_t)bl) << 9) + c) = acc;
}

// out = s - movavg25(s), s = in1 + in2, edge-replicated (clamped) window
__global__ __launch_bounds__(256)
void decomp_kernel(const float* __restrict__ in1, const float* __restrict__ in2,
                   float* __restrict__ outp)
{
    __shared__ float s[152][64];
    int b = blockIdx.x, lt = blockIdx.y, dt = blockIdx.z;
    int l0 = lt << 7, d0 = dt << 6;
    int tid = threadIdx.x;
    for (int i = tid; i < 152*64; i += 256) {
        int r = i >> 6, d = i & 63;
        int l = l0 - 12 + r;
        l = l < 0 ? 0 : (l > 1023 ? 1023 : l);
        size_t gi = (((((size_t)b) << 10) + l) << 9) + d0 + d;
        s[r][d] = in1[gi] + in2[gi];
    }
    __syncthreads();
    int d = tid & 63, ch = tid >> 6;
    int lb = ch << 5;
    float sum = 0.f;
#pragma unroll
    for (int j = 0; j < 25; j++) sum += s[lb + j][d];
    for (int i = 0; i < 32; i++) {
        size_t gi = (((((size_t)b) << 10) + (l0 + lb + i)) << 9) + d0 + d;
        outp[gi] = s[lb + 12 + i][d] - sum * (1.f/25.f);
        if (i != 31) sum += s[lb + 25 + i][d] - s[lb + i][d];
    }
}

// layernorm (over D) with gamma/beta
__global__ __launch_bounds__(128)
void ln_kernel(const float* __restrict__ h, const float* __restrict__ gam,
               const float* __restrict__ bet, float* __restrict__ hn)
{
    int row = blockIdx.x;
    int t = threadIdx.x;
    const float4 x = *(const float4*)(h + (((size_t)row) << 9) + (t << 2));
    float s1 = x.x + x.y + x.z + x.w;
    float s2 = x.x*x.x + x.y*x.y + x.z*x.z + x.w*x.w;
#pragma unroll
    for (int o = 16; o > 0; o >>= 1) {
        s1 += __shfl_xor_sync(0xffffffffu, s1, o);
        s2 += __shfl_xor_sync(0xffffffffu, s2, o);
    }
    __shared__ float a1[4], a2[4];
    if ((t & 31) == 0) { a1[t >> 5] = s1; a2[t >> 5] = s2; }
    __syncthreads();
    s1 = a1[0] + a1[1] + a1[2] + a1[3];
    s2 = a2[0] + a2[1] + a2[2] + a2[3];
    float mu  = s1 * (1.f/512.f);
    float var = s2 * (1.f/512.f) - mu*mu;
    float rs  = rsqrtf(var + 1e-5f);
    int c = t << 2;
    float4 o4;
    o4.x = (x.x - mu)*rs*gam[c+0] + bet[c+0];
    o4.y = (x.y - mu)*rs*gam[c+1] + bet[c+1];
    o4.z = (x.z - mu)*rs*gam[c+2] + bet[c+2];
    o4.w = (x.w - mu)*rs*gam[c+3] + bet[c+3];
    *(float4*)(hn + (((size_t)row) << 9) + c) = o4;
}

// per-(b,d) mean over L of hn
__global__ __launch_bounds__(128)
void colmean_kernel(const float* __restrict__ hn, float* __restrict__ cm)
{
    int b = blockIdx.x;
    int d = blockIdx.y * 128 + threadIdx.x;
    float s = 0.f;
    const float* p = hn + ((((size_t)b) << 10) << 9) + d;
    for (int l = 0; l < 1024; l++) s += p[((size_t)l) << 9];
    cm[(b << 9) + d] = s * (1.f/1024.f);
}

// cb[b,n] = colmean[b,:] @ proj_w[:,n]
__global__ __launch_bounds__(64)
void cbias_kernel(const float* __restrict__ cm, const float* __restrict__ pw,
                  float* __restrict__ cb)
{
    int b = blockIdx.x, n = threadIdx.x;
    float s = 0.f;
    for (int d2 = 0; d2 < 512; d2++) s = fmaf(cm[(b << 9) + d2], pw[d2*64 + n], s);
    cb[(b << 6) + n] = s;
}

// out[b,l,n] -= cb[b,n]
__global__ void sub_kernel(float* __restrict__ outp, const float* __restrict__ cb)
{
    int i = blockIdx.x * blockDim.x + threadIdx.x;
    if (i >= MROWS*64) return;
    outp[i] -= cb[((i >> 16) << 6) + (i & 63)];
}

// ---------------- host launcher ----------------
extern "C" void kernel_launch(void* const* d_in, const int* in_sizes, int n_in,
                              void* d_out, int out_size)
{
    const float* x       = (const float*)d_in[0];
    const float* embed_w = (const float*)d_in[1];
    const float* wq = (const float*)d_in[2];  const float* bq = (const float*)d_in[3];
    const float* wk = (const float*)d_in[4];  const float* bk = (const float*)d_in[5];
    const float* wv = (const float*)d_in[6];  const float* bv = (const float*)d_in[7];
    const float* wo = (const float*)d_in[8];  const float* bo = (const float*)d_in[9];
    const float* w1 = (const float*)d_in[10]; const float* w2 = (const float*)d_in[11];
    const float* ln_g = (const float*)d_in[12]; const float* ln_b = (const float*)d_in[13];
    const float* pw = (const float*)d_in[14]; const float* pb = (const float*)d_in[15];
    float* outp = (float*)d_out;
    (void)in_sizes; (void)n_in; (void)out_size;

    float *h, *h2, *q, *k, *v, *a, *t, *ffn, *xc, *corr, *tcw, *cm, *cb;
    float2* sp; int* dly;
    cudaGetSymbolAddress((void**)&h,   g_h);
    cudaGetSymbolAddress((void**)&h2,  g_h2);
    cudaGetSymbolAddress((void**)&q,   g_q);
    cudaGetSymbolAddress((void**)&k,   g_k);
    cudaGetSymbolAddress((void**)&v,   g_v);
    cudaGetSymbolAddress((void**)&a,   g_a);
    cudaGetSymbolAddress((void**)&t,   g_t);
    cudaGetSymbolAddress((void**)&ffn, g_ffn);
    cudaGetSymbolAddress((void**)&xc,  g_xcat);
    cudaGetSymbolAddress((void**)&sp,  g_Spart);
    cudaGetSymbolAddress((void**)&corr,g_corr);
    cudaGetSymbolAddress((void**)&tcw, g_tcw);
    cudaGetSymbolAddress((void**)&dly, g_dly);
    cudaGetSymbolAddress((void**)&cm,  g_cm);
    cudaGetSymbolAddress((void**)&cb,  g_cb);

    dim3 gN512(4, MROWS/128);
    dim3 gN2048(16, MROWS/128);
    dim3 gN64(1, MROWS/128);

    // token embedding (circular conv1d k=3 as gather + GEMM)
    xcat_kernel<<<(MROWS*192 + 255)/256, 256>>>(x, xc);
    sgemm_kernel<0><<<gN512, 256>>>(xc, embed_w, nullptr, h, MROWS, 512, 192);

    for (int l = 0; l < NL_; l++) {
        const float* wql = wq + (size_t)l*D_*D_;  const float* bql = bq + l*D_;
        const float* wkl = wk + (size_t)l*D_*D_;  const float* bkl = bk + l*D_;
        const float* wvl = wv + (size_t)l*D_*D_;  const float* bvl = bv + l*D_;
        const float* wol = wo + (size_t)l*D_*D_;  const float* bol = bo + l*D_;
        const float* w1l = w1 + (size_t)l*D_*DFF_;
        const float* w2l = w2 + (size_t)l*DFF_*D_;

        sgemm_kernel<0><<<gN512, 256>>>(h, wql, bql, q, MROWS, 512, 512);
        sgemm_kernel<0><<<gN512, 256>>>(h, wkl, bkl, k, MROWS, 512, 512);
        sgemm_kernel<0><<<gN512, 256>>>(h, wvl, bvl, v, MROWS, 512, 512);

        corr_fft_kernel <<<dim3(B_, 32), 256>>>(q, k, sp);
        corr_ifft_kernel<<<B_, 256>>>(sp, corr);
        topk_kernel     <<<B_, 256>>>(corr, tcw, dly);
        agg_kernel      <<<MROWS, 128>>>(v, tcw, dly, a);

        sgemm_kernel<0><<<gN512, 256>>>(a, wol, bol, t, MROWS, 512, 512);
        decomp_kernel<<<dim3(B_, 8, 8), 256>>>(h, t, h2);

        sgemm_kernel<1><<<gN2048, 256>>>(h2, w1l, nullptr, ffn, MROWS, 2048, 512);
        sgemm_kernel<0><<<gN512, 256>>>(ffn, w2l, nullptr, t, MROWS, 512, 2048);
        decomp_kernel<<<dim3(B_, 8, 8), 256>>>(h2, t, h);
    }

    // final my_Layernorm + time-mean subtraction + projection
    ln_kernel<<<MROWS, 128>>>(h, ln_g, ln_b, q);            // hn -> g_q
    colmean_kernel<<<dim3(B_, 4), 128>>>(q, cm);
    cbias_kernel<<<B_, 64>>>(cm, pw, cb);
    sgemm_kernel<0><<<gN64, 256>>>(q, pw, pb, outp, MROWS, 64, 512);
    sub_kernel<<<(MROWS*64 + 255)/256, 256>>>(outp, cb);
}

// round 6
// speedup vs baseline: 1.0029x; 1.0000x over previous
#include <cuda_runtime.h>
#include <math.h>
#include <stdint.h>

#define B_    32
#define L_    1024
#define CIN_  64
#define D_    512
#define DFF_  2048
#define NL_   3
#define TOPK_ 6
#define MROWS (B_*L_)   /* 32768 */

// ---------------- scratch (device globals; allocation-free) ----------------
__device__ float  g_h  [MROWS*D_];
__device__ float  g_h2 [MROWS*D_];
__device__ float  g_q  [MROWS*D_];
__device__ float  g_k  [MROWS*D_];
__device__ float  g_v  [MROWS*D_];
__device__ float  g_a  [MROWS*D_];
__device__ float  g_t  [MROWS*D_];
__device__ float  g_ffn[MROWS*DFF_];
__device__ float  g_xcat[MROWS*3*CIN_];
__device__ float2 g_Spart[B_*32*L_];
__device__ float  g_corr[B_*L_];
__device__ float  g_tcw [B_*TOPK_];
__device__ int    g_dly [B_*TOPK_];
__device__ float  g_cm  [B_*D_];
__device__ float  g_cb  [B_*CIN_];

// ---------------- complex helpers ----------------
__device__ __forceinline__ float2 cadd(float2 a, float2 b){ return make_float2(a.x+b.x, a.y+b.y); }
__device__ __forceinline__ float2 csub(float2 a, float2 b){ return make_float2(a.x-b.x, a.y-b.y); }
__device__ __forceinline__ float2 cmul(float2 a, float2 b){ return make_float2(a.x*b.x-a.y*b.y, a.x*b.y+a.y*b.x); }

// ---------------- circular-pad gather for token embedding ----------------
__global__ void xcat_kernel(const float* __restrict__ x, float* __restrict__ xc)
{
    int idx = blockIdx.x*blockDim.x + threadIdx.x;
    if (idx >= MROWS*192) return;
    int row = idx / 192, cc = idx % 192;
    int j = cc >> 6, c = cc & 63;
    int b = row >> 10, l = row & 1023;
    int ls = (l + j + 1023) & 1023;          // (l + j - 1) mod L
    xc[idx] = x[((((size_t)b)<<10) + ls)*64 + c];
}

// ---------------- fp32 SGEMM: C = A(MxK) * B(KxN) [+bias][gelu] ----------------
template<int GELU>
__global__ __launch_bounds__(256)
void sgemm_kernel(const float* __restrict__ A, const float* __restrict__ Bm,
                  const float* __restrict__ bias, float* __restrict__ C,
                  int M, int N, int K)
{
    __shared__ float As[16][128];
    __shared__ float Bs[16][128];
    int tid = threadIdx.x;
    int tx = tid & 15, ty = tid >> 4;
    int bx = blockIdx.x, by = blockIdx.y;

    int aRow = tid >> 2;
    int aCol = (tid & 3) << 2;
    int bRow = tid >> 5;
    int bCol = (tid & 31) << 2;

    const float* Ab = A + ((size_t)by * 128) * (size_t)K;

    float acc[8][8];
#pragma unroll
    for (int i = 0; i < 8; i++)
#pragma unroll
        for (int j = 0; j < 8; j++) acc[i][j] = 0.f;

    for (int k0 = 0; k0 < K; k0 += 16) {
#pragma unroll
        for (int i = 0; i < 2; i++) {
            float4 va = *(const float4*)(Ab + (size_t)(aRow + i*64)*K + k0 + aCol);
            As[aCol+0][aRow+i*64] = va.x;
            As[aCol+1][aRow+i*64] = va.y;
            As[aCol+2][aRow+i*64] = va.z;
            As[aCol+3][aRow+i*64] = va.w;
        }
#pragma unroll
        for (int i = 0; i < 2; i++) {
            int c = bx*128 + bCol;
            float4 vb = make_float4(0.f,0.f,0.f,0.f);
            if (c < N) vb = *(const float4*)(Bm + (size_t)(k0 + bRow + i*8)*N + c);
            *(float4*)&Bs[bRow+i*8][bCol] = vb;
        }
        __syncthreads();
#pragma unroll
        for (int kk = 0; kk < 16; kk++) {
            float ar[8], br[8];
            *(float4*)&ar[0] = *(const float4*)&As[kk][ty*8];
            *(float4*)&ar[4] = *(const float4*)&As[kk][ty*8+4];
            *(float4*)&br[0] = *(const float4*)&Bs[kk][tx*8];
            *(float4*)&br[4] = *(const float4*)&Bs[kk][tx*8+4];
#pragma unroll
            for (int i = 0; i < 8; i++)
#pragma unroll
                for (int j = 0; j < 8; j++)
                    acc[i][j] = fmaf(ar[i], br[j], acc[i][j]);
        }
        __syncthreads();
    }

#pragma unroll
    for (int i = 0; i < 8; i++) {
        int r = by*128 + ty*8 + i;
        float* crow = C + (size_t)r * (size_t)N;
#pragma unroll
        for (int jj = 0; jj < 8; jj += 4) {
            int c = bx*128 + tx*8 + jj;
            if (c < N) {
                float4 v;
                v.x = acc[i][jj+0]; v.y = acc[i][jj+1];
                v.z = acc[i][jj+2]; v.w = acc[i][jj+3];
                if (bias != nullptr) {
                    v.x += bias[c+0]; v.y += bias[c+1];
                    v.z += bias[c+2]; v.w += bias[c+3];
                }
                if (GELU) {
                    v.x = 0.5f*v.x*(1.f + erff(v.x*0.7071067811865475f));
                    v.y = 0.5f*v.y*(1.f + erff(v.y*0.7071067811865475f));
                    v.z = 0.5f*v.z*(1.f + erff(v.z*0.7071067811865475f));
                    v.w = 0.5f*v.w*(1.f + erff(v.w*0.7071067811865475f));
                }
                *(float4*)(crow + c) = v;
            }
        }
    }
}

// ---------------- length-1024 in-place radix-2 FFT (input bit-reversed) ----------------
__device__ void fft1024(float2* z, const float2* tw)
{
    int tid = threadIdx.x;   // blockDim == 256
    for (int half = 1; half < 1024; half <<= 1) {
        int step = 512 / half;
#pragma unroll 2
        for (int idx = tid; idx < 512; idx += 256) {
            int j = idx & (half - 1);
            int base = (idx & ~(half - 1)) << 1;
            float2 w = tw[j * step];
            float2 u = z[base + j];
            float2 t = cmul(w, z[base + j + half]);
            z[base + j]        = cadd(u, t);
            z[base + j + half] = csub(u, t);
        }
        __syncthreads();
    }
}

// S_partial[b,g,f] = sum over 16 channels of Q_d[f] * conj(K_d[f])
__global__ __launch_bounds__(256)
void corr_fft_kernel(const float* __restrict__ q, const float* __restrict__ k,
                     float2* __restrict__ Spart)
{
    __shared__ float2 z[1024];
    __shared__ float2 acc[1024];
    __shared__ float2 tw[512];
    int tid = threadIdx.x;
    int b = blockIdx.x, g = blockIdx.y;

    for (int i = tid; i < 512; i += 256) {
        float s, c;
        sincosf(-6.283185307179586f * (float)i / 1024.f, &s, &c);
        tw[i] = make_float2(c, s);
    }
    for (int i = tid; i < 1024; i += 256) acc[i] = make_float2(0.f, 0.f);
    __syncthreads();

    const float* qb = q + (((size_t)b) << 10) * 512;
    const float* kb = k + (((size_t)b) << 10) * 512;

    for (int dd = 0; dd < 16; dd++) {
        int d = (g << 4) + dd;
        for (int t = tid; t < 1024; t += 256) {
            int r = __brev((unsigned)t) >> 22;
            z[r] = make_float2(qb[(((size_t)t) << 9) + d], kb[(((size_t)t) << 9) + d]);
        }
        __syncthreads();
        fft1024(z, tw);
        for (int f = tid; f < 1024; f += 256) {
            float2 Zf = z[f];
            float2 Zm = z[(1024 - f) & 1023];
            float Qx = 0.5f*(Zf.x + Zm.x), Qy = 0.5f*(Zf.y - Zm.y);
            float Kx = 0.5f*(Zf.y + Zm.y), Ky = 0.5f*(Zm.x - Zf.x);
            // P = Q * conj(K)
            float2 P = make_float2(Qx*Kx + Qy*Ky, Qy*Kx - Qx*Ky);
            acc[f] = cadd(acc[f], P);
        }
        __syncthreads();
    }
    float2* outp = Spart + ((((size_t)b) << 5) + g) * 1024;
    for (int f = tid; f < 1024; f += 256) outp[f] = acc[f];
}

// mean_corr[b,tau] = Re(ifft(sum_g Spart))[tau] / 512
__global__ __launch_bounds__(256)
void corr_ifft_kernel(const float2* __restrict__ Spart, float* __restrict__ corr)
{
    __shared__ float2 z[1024];
    __shared__ float2 tw[512];
    int tid = threadIdx.x;
    int b = blockIdx.x;

    for (int i = tid; i < 512; i += 256) {
        float s, c;
        sincosf(6.283185307179586f * (float)i / 1024.f, &s, &c);
        tw[i] = make_float2(c, s);
    }
    __syncthreads();
    for (int t = tid; t < 1024; t += 256) {
        float2 s = make_float2(0.f, 0.f);
        const float2* sp = Spart + ((((size_t)b) << 5) * 1024) + t;
        for (int g2 = 0; g2 < 32; g2++) s = cadd(s, sp[(size_t)g2 << 10]);
        z[__brev((unsigned)t) >> 22] = s;
    }
    __syncthreads();
    fft1024(z, tw);
    const float scale = 1.f / (1024.f * 512.f);
    for (int t = tid; t < 1024; t += 256)
        corr[(b << 10) + t] = z[t].x * scale;
}

// top-6 + softmax per batch
__global__ __launch_bounds__(256)
void topk_kernel(const float* __restrict__ corr, float* __restrict__ tcw, int* __restrict__ dly)
{
    int b = blockIdx.x, t = threadIdx.x;
    __shared__ float vals[1024];
    __shared__ float rv[256];
    __shared__ int   ri[256];
    __shared__ float wv[TOPK_];
    __shared__ int   wi[TOPK_];
    for (int i = t; i < 1024; i += 256) vals[i] = corr[(b << 10) + i];
    __syncthreads();
    for (int kk = 0; kk < TOPK_; kk++) {
        float bm = -INFINITY; int bi = 0x7fffffff;
        for (int i = t; i < 1024; i += 256) {
            float v = vals[i];
            if (v > bm || (v == bm && i < bi)) { bm = v; bi = i; }
        }
        rv[t] = bm; ri[t] = bi;
        __syncthreads();
        for (int s = 128; s > 0; s >>= 1) {
            if (t < s) {
                if (rv[t+s] > rv[t] || (rv[t+s] == rv[t] && ri[t+s] < ri[t])) {
                    rv[t] = rv[t+s]; ri[t] = ri[t+s];
                }
            }
            __syncthreads();
        }
        if (t == 0) { wv[kk] = rv[0]; wi[kk] = ri[0]; vals[ri[0]] = -INFINITY; }
        __syncthreads();
    }
    if (t == 0) {
        float m = wv[0];
        for (int kk = 1; kk < TOPK_; kk++) m = fmaxf(m, wv[kk]);
        float e[TOPK_], s = 0.f;
        for (int kk = 0; kk < TOPK_; kk++) { e[kk] = expf(wv[kk] - m); s += e[kk]; }
        float inv = 1.f / s;
        for (int kk = 0; kk < TOPK_; kk++) {
            tcw[b*TOPK_ + kk] = e[kk] * inv;
            dly[b*TOPK_ + kk] = wi[kk];
        }
    }
}

// a[b,l,:] = sum_k tc_k * v[b,(l+delay_k)%L,:]
__global__ __launch_bounds__(128)
void agg_kernel(const float* __restrict__ v, const float* __restrict__ tcw,
                const int* __restrict__ dly, float* __restrict__ outp)
{
    int bl = blockIdx.x;
    int b = bl >> 10, l = bl & 1023;
    __shared__ float w[TOPK_];
    __shared__ int   dd[TOPK_];
    if (threadIdx.x < TOPK_) {
        w[threadIdx.x]  = tcw[b*TOPK_ + threadIdx.x];
        dd[threadIdx.x] = dly[b*TOPK_ + threadIdx.x];
    }
    __syncthreads();
    int c = threadIdx.x << 2;
    float4 acc = make_float4(0.f, 0.f, 0.f, 0.f);
#pragma unroll
    for (int kk = 0; kk < TOPK_; kk++) {
        int row = (l + dd[kk]) & 1023;
        float4 vv = *(const float4*)(v + (((((size_t)b) << 10) + row) << 9) + c);
        acc.x = fmaf(w[kk], vv.x, acc.x);
        acc.y = fmaf(w[kk], vv.y, acc.y);
        acc.z = fmaf(w[kk], vv.z, acc.z);
        acc.w = fmaf(w[kk], vv.w, acc.w);
    }
    *(float4*)(outp + (((size_t)bl) << 9) + c) = acc;
}

// out = s - movavg25(s), s = in1 + in2, edge-replicated (clamped) window
__global__ __launch_bounds__(256)
void decomp_kernel(const float* __restrict__ in1, const float* __restrict__ in2,
                   float* __restrict__ outp)
{
    __shared__ float s[152][64];
    int b = blockIdx.x, lt = blockIdx.y, dt = blockIdx.z;
    int l0 = lt << 7, d0 = dt << 6;
    int tid = threadIdx.x;
    for (int i = tid; i < 152*64; i += 256) {
        int r = i >> 6, d = i & 63;
        int l = l0 - 12 + r;
        l = l < 0 ? 0 : (l > 1023 ? 1023 : l);
        size_t gi = (((((size_t)b) << 10) + l) << 9) + d0 + d;
        s[r][d] = in1[gi] + in2[gi];
    }
    __syncthreads();
    int d = tid & 63, ch = tid >> 6;
    int lb = ch << 5;
    float sum = 0.f;
#pragma unroll
    for (int j = 0; j < 25; j++) sum += s[lb + j][d];
    for (int i = 0; i < 32; i++) {
        size_t gi = (((((size_t)b) << 10) + (l0 + lb + i)) << 9) + d0 + d;
        outp[gi] = s[lb + 12 + i][d] - sum * (1.f/25.f);
        if (i != 31) sum += s[lb + 25 + i][d] - s[lb + i][d];
    }
}

// layernorm (over D) with gamma/beta
__global__ __launch_bounds__(128)
void ln_kernel(const float* __restrict__ h, const float* __restrict__ gam,
               const float* __restrict__ bet, float* __restrict__ hn)
{
    int row = blockIdx.x;
    int t = threadIdx.x;
    const float4 x = *(const float4*)(h + (((size_t)row) << 9) + (t << 2));
    float s1 = x.x + x.y + x.z + x.w;
    float s2 = x.x*x.x + x.y*x.y + x.z*x.z + x.w*x.w;
#pragma unroll
    for (int o = 16; o > 0; o >>= 1) {
        s1 += __shfl_xor_sync(0xffffffffu, s1, o);
        s2 += __shfl_xor_sync(0xffffffffu, s2, o);
    }
    __shared__ float a1[4], a2[4];
    if ((t & 31) == 0) { a1[t >> 5] = s1; a2[t >> 5] = s2; }
    __syncthreads();
    s1 = a1[0] + a1[1] + a1[2] + a1[3];
    s2 = a2[0] + a2[1] + a2[2] + a2[3];
    float mu  = s1 * (1.f/512.f);
    float var = s2 * (1.f/512.f) - mu*mu;
    float rs  = rsqrtf(var + 1e-5f);
    int c = t << 2;
    float4 o4;
    o4.x = (x.x - mu)*rs*gam[c+0] + bet[c+0];
    o4.y = (x.y - mu)*rs*gam[c+1] + bet[c+1];
    o4.z = (x.z - mu)*rs*gam[c+2] + bet[c+2];
    o4.w = (x.w - mu)*rs*gam[c+3] + bet[c+3];
    *(float4*)(hn + (((size_t)row) << 9) + c) = o4;
}

// per-(b,d) mean over L of hn
__global__ __launch_bounds__(128)
void colmean_kernel(const float* __restrict__ hn, float* __restrict__ cm)
{
    int b = blockIdx.x;
    int d = blockIdx.y * 128 + threadIdx.x;
    float s = 0.f;
    const float* p = hn + ((((size_t)b) << 10) << 9) + d;
    for (int l = 0; l < 1024; l++) s += p[((size_t)l) << 9];
    cm[(b << 9) + d] = s * (1.f/1024.f);
}

// cb[b,n] = colmean[b,:] @ proj_w[:,n]
__global__ __launch_bounds__(64)
void cbias_kernel(const float* __restrict__ cm, const float* __restrict__ pw,
                  float* __restrict__ cb)
{
    int b = blockIdx.x, n = threadIdx.x;
    float s = 0.f;
    for (int d2 = 0; d2 < 512; d2++) s = fmaf(cm[(b << 9) + d2], pw[d2*64 + n], s);
    cb[(b << 6) + n] = s;
}

// out[b,l,n] -= cb[b,n]
__global__ void sub_kernel(float* __restrict__ outp, const float* __restrict__ cb)
{
    int i = blockIdx.x * blockDim.x + threadIdx.x;
    if (i >= MROWS*64) return;
    outp[i] -= cb[((i >> 16) << 6) + (i & 63)];
}

// ---------------- host launcher ----------------
extern "C" void kernel_launch(void* const* d_in, const int* in_sizes, int n_in,
                              void* d_out, int out_size)
{
    const float* x       = (const float*)d_in[0];
    const float* embed_w = (const float*)d_in[1];
    const float* wq = (const float*)d_in[2];  const float* bq = (const float*)d_in[3];
    const float* wk = (const float*)d_in[4];  const float* bk = (const float*)d_in[5];
    const float* wv = (const float*)d_in[6];  const float* bv = (const float*)d_in[7];
    const float* wo = (const float*)d_in[8];  const float* bo = (const float*)d_in[9];
    const float* w1 = (const float*)d_in[10]; const float* w2 = (const float*)d_in[11];
    const float* ln_g = (const float*)d_in[12]; const float* ln_b = (const float*)d_in[13];
    const float* pw = (const float*)d_in[14]; const float* pb = (const float*)d_in[15];
    float* outp = (float*)d_out;
    (void)in_sizes; (void)n_in; (void)out_size;

    float *h, *h2, *q, *k, *v, *a, *t, *ffn, *xc, *corr, *tcw, *cm, *cb;
    float2* sp; int* dly;
    cudaGetSymbolAddress((void**)&h,   g_h);
    cudaGetSymbolAddress((void**)&h2,  g_h2);
    cudaGetSymbolAddress((void**)&q,   g_q);
    cudaGetSymbolAddress((void**)&k,   g_k);
    cudaGetSymbolAddress((void**)&v,   g_v);
    cudaGetSymbolAddress((void**)&a,   g_a);
    cudaGetSymbolAddress((void**)&t,   g_t);
    cudaGetSymbolAddress((void**)&ffn, g_ffn);
    cudaGetSymbolAddress((void**)&xc,  g_xcat);
    cudaGetSymbolAddress((void**)&sp,  g_Spart);
    cudaGetSymbolAddress((void**)&corr,g_corr);
    cudaGetSymbolAddress((void**)&tcw, g_tcw);
    cudaGetSymbolAddress((void**)&dly, g_dly);
    cudaGetSymbolAddress((void**)&cm,  g_cm);
    cudaGetSymbolAddress((void**)&cb,  g_cb);

    dim3 gN512(4, MROWS/128);
    dim3 gN2048(16, MROWS/128);
    dim3 gN64(1, MROWS/128);

    // token embedding (circular conv1d k=3 as gather + GEMM)
    xcat_kernel<<<(MROWS*192 + 255)/256, 256>>>(x, xc);
    sgemm_kernel<0><<<gN512, 256>>>(xc, embed_w, nullptr, h, MROWS, 512, 192);

    for (int l = 0; l < NL_; l++) {
        const float* wql = wq + (size_t)l*D_*D_;  const float* bql = bq + l*D_;
        const float* wkl = wk + (size_t)l*D_*D_;  const float* bkl = bk + l*D_;
        const float* wvl = wv + (size_t)l*D_*D_;  const float* bvl = bv + l*D_;
        const float* wol = wo + (size_t)l*D_*D_;  const float* bol = bo + l*D_;
        const float* w1l = w1 + (size_t)l*D_*DFF_;
        const float* w2l = w2 + (size_t)l*DFF_*D_;

        sgemm_kernel<0><<<gN512, 256>>>(h, wql, bql, q, MROWS, 512, 512);
        sgemm_kernel<0><<<gN512, 256>>>(h, wkl, bkl, k, MROWS, 512, 512);
        sgemm_kernel<0><<<gN512, 256>>>(h, wvl, bvl, v, MROWS, 512, 512);

        corr_fft_kernel <<<dim3(B_, 32), 256>>>(q, k, sp);
        corr_ifft_kernel<<<B_, 256>>>(sp, corr);
        topk_kernel     <<<B_, 256>>>(corr, tcw, dly);
        agg_kernel      <<<MROWS, 128>>>(v, tcw, dly, a);

        sgemm_kernel<0><<<gN512, 256>>>(a, wol, bol, t, MROWS, 512, 512);
        decomp_kernel<<<dim3(B_, 8, 8), 256>>>(h, t, h2);

        sgemm_kernel<1><<<gN2048, 256>>>(h2, w1l, nullptr, ffn, MROWS, 2048, 512);
        sgemm_kernel<0><<<gN512, 256>>>(ffn, w2l, nullptr, t, MROWS, 512, 2048);
        decomp_kernel<<<dim3(B_, 8, 8), 256>>>(h2, t, h);
    }

    // final my_Layernorm + time-mean subtraction + projection
    ln_kernel<<<MROWS, 128>>>(h, ln_g, ln_b, q);            // hn -> g_q
    colmean_kernel<<<dim3(B_, 4), 128>>>(q, cm);
    cbias_kernel<<<B_, 64>>>(cm, pw, cb);
    sgemm_kernel<0><<<gN64, 256>>>(q, pw, pb, outp, MROWS, 64, 512);
    sub_kernel<<<(MROWS*64 + 255)/256, 256>>>(outp, cb);
}

// round 7
// speedup vs baseline: 1.0031x; 1.0002x over previous
#include <cuda_runtime.h>
#include <math.h>
#include <stdint.h>

#define B_    32
#define L_    1024
#define CIN_  64
#define D_    512
#define DFF_  2048
#define NL_   3
#define TOPK_ 6
#define MROWS (B_*L_)   /* 32768 */

// ---------------- scratch (device globals; allocation-free) ----------------
__device__ float  g_h  [MROWS*D_];
__device__ float  g_h2 [MROWS*D_];
__device__ float  g_q  [MROWS*D_];
__device__ float  g_k  [MROWS*D_];
__device__ float  g_v  [MROWS*D_];
__device__ float  g_a  [MROWS*D_];
__device__ float  g_t  [MROWS*D_];
__device__ float  g_ffn[MROWS*DFF_];
__device__ float  g_xcat[MROWS*3*CIN_];
__device__ float2 g_Spart[B_*32*L_];
__device__ float  g_corr[B_*L_];
__device__ float  g_tcw [B_*TOPK_];
__device__ int    g_dly [B_*TOPK_];
__device__ float  g_cm  [B_*D_];
__device__ float  g_cb  [B_*CIN_];

// ---------------- complex helpers ----------------
__device__ __forceinline__ float2 cadd(float2 a, float2 b){ return make_float2(a.x+b.x, a.y+b.y); }
__device__ __forceinline__ float2 csub(float2 a, float2 b){ return make_float2(a.x-b.x, a.y-b.y); }
__device__ __forceinline__ float2 cmul(float2 a, float2 b){ return make_float2(a.x*b.x-a.y*b.y, a.x*b.y+a.y*b.x); }

// ---------------- circular-pad gather for token embedding ----------------
__global__ void xcat_kernel(const float* __restrict__ x, float* __restrict__ xc)
{
    int idx = blockIdx.x*blockDim.x + threadIdx.x;
    if (idx >= MROWS*192) return;
    int row = idx / 192, cc = idx % 192;
    int j = cc >> 6, c = cc & 63;
    int b = row >> 10, l = row & 1023;
    int ls = (l + j + 1023) & 1023;          // (l + j - 1) mod L
    xc[idx] = x[((((size_t)b)<<10) + ls)*64 + c];
}

// ---------------- fp32 SGEMM: C = A(MxK) * B(KxN) [+bias][gelu] ----------------
template<int GELU>
__global__ __launch_bounds__(256)
void sgemm_kernel(const float* __restrict__ A, const float* __restrict__ Bm,
                  const float* __restrict__ bias, float* __restrict__ C,
                  int M, int N, int K)
{
    __shared__ float As[16][128];
    __shared__ float Bs[16][128];
    int tid = threadIdx.x;
    int tx = tid & 15, ty = tid >> 4;
    int bx = blockIdx.x, by = blockIdx.y;

    int aRow = tid >> 2;
    int aCol = (tid & 3) << 2;
    int bRow = tid >> 5;
    int bCol = (tid & 31) << 2;

    const float* Ab = A + ((size_t)by * 128) * (size_t)K;

    float acc[8][8];
#pragma unroll
    for (int i = 0; i < 8; i++)
#pragma unroll
        for (int j = 0; j < 8; j++) acc[i][j] = 0.f;

    for (int k0 = 0; k0 < K; k0 += 16) {
#pragma unroll
        for (int i = 0; i < 2; i++) {
            float4 va = *(const float4*)(Ab + (size_t)(aRow + i*64)*K + k0 + aCol);
            As[aCol+0][aRow+i*64] = va.x;
            As[aCol+1][aRow+i*64] = va.y;
            As[aCol+2][aRow+i*64] = va.z;
            As[aCol+3][aRow+i*64] = va.w;
        }
#pragma unroll
        for (int i = 0; i < 2; i++) {
            int c = bx*128 + bCol;
            float4 vb = make_float4(0.f,0.f,0.f,0.f);
            if (c < N) vb = *(const float4*)(Bm + (size_t)(k0 + bRow + i*8)*N + c);
            *(float4*)&Bs[bRow+i*8][bCol] = vb;
        }
        __syncthreads();
#pragma unroll
        for (int kk = 0; kk < 16; kk++) {
            float ar[8], br[8];
            *(float4*)&ar[0] = *(const float4*)&As[kk][ty*8];
            *(float4*)&ar[4] = *(const float4*)&As[kk][ty*8+4];
            *(float4*)&br[0] = *(const float4*)&Bs[kk][tx*8];
            *(float4*)&br[4] = *(const float4*)&Bs[kk][tx*8+4];
#pragma unroll
            for (int i = 0; i < 8; i++)
#pragma unroll
                for (int j = 0; j < 8; j++)
                    acc[i][j] = fmaf(ar[i], br[j], acc[i][j]);
        }
        __syncthreads();
    }

#pragma unroll
    for (int i = 0; i < 8; i++) {
        int r = by*128 + ty*8 + i;
        float* crow = C + (size_t)r * (size_t)N;
#pragma unroll
        for (int jj = 0; jj < 8; jj += 4) {
            int c = bx*128 + tx*8 + jj;
            if (c < N) {
                float4 v;
                v.x = acc[i][jj+0]; v.y = acc[i][jj+1];
                v.z = acc[i][jj+2]; v.w = acc[i][jj+3];
                if (bias != nullptr) {
                    v.x += bias[c+0]; v.y += bias[c+1];
                    v.z += bias[c+2]; v.w += bias[c+3];
                }
                if (GELU) {
                    v.x = 0.5f*v.x*(1.f + erff(v.x*0.7071067811865475f));
                    v.y = 0.5f*v.y*(1.f + erff(v.y*0.7071067811865475f));
                    v.z = 0.5f*v.z*(1.f + erff(v.z*0.7071067811865475f));
                    v.w = 0.5f*v.w*(1.f + erff(v.w*0.7071067811865475f));
                }
                *(float4*)(crow + c) = v;
            }
        }
    }
}

// ---------------- length-1024 in-place radix-2 FFT (input bit-reversed) ----------------
__device__ void fft1024(float2* z, const float2* tw)
{
    int tid = threadIdx.x;   // blockDim == 256
    for (int half = 1; half < 1024; half <<= 1) {
        int step = 512 / half;
#pragma unroll 2
        for (int idx = tid; idx < 512; idx += 256) {
            int j = idx & (half - 1);
            int base = (idx & ~(half - 1)) << 1;
            float2 w = tw[j * step];
            float2 u = z[base + j];
            float2 t = cmul(w, z[base + j + half]);
            z[base + j]        = cadd(u, t);
            z[base + j + half] = csub(u, t);
        }
        __syncthreads();
    }
}

// S_partial[b,g,f] = sum over 16 channels of Q_d[f] * conj(K_d[f])
__global__ __launch_bounds__(256)
void corr_fft_kernel(const float* __restrict__ q, const float* __restrict__ k,
                     float2* __restrict__ Spart)
{
    __shared__ float2 z[1024];
    __shared__ float2 acc[1024];
    __shared__ float2 tw[512];
    int tid = threadIdx.x;
    int b = blockIdx.x, g = blockIdx.y;

    for (int i = tid; i < 512; i += 256) {
        float s, c;
        sincosf(-6.283185307179586f * (float)i / 1024.f, &s, &c);
        tw[i] = make_float2(c, s);
    }
    for (int i = tid; i < 1024; i += 256) acc[i] = make_float2(0.f, 0.f);
    __syncthreads();

    const float* qb = q + (((size_t)b) << 10) * 512;
    const float* kb = k + (((size_t)b) << 10) * 512;

    for (int dd = 0; dd < 16; dd++) {
        int d = (g << 4) + dd;
        for (int t = tid; t < 1024; t += 256) {
            int r = __brev((unsigned)t) >> 22;
            z[r] = make_float2(qb[(((size_t)t) << 9) + d], kb[(((size_t)t) << 9) + d]);
        }
        __syncthreads();
        fft1024(z, tw);
        for (int f = tid; f < 1024; f += 256) {
            float2 Zf = z[f];
            float2 Zm = z[(1024 - f) & 1023];
            float Qx = 0.5f*(Zf.x + Zm.x), Qy = 0.5f*(Zf.y - Zm.y);
            float Kx = 0.5f*(Zf.y + Zm.y), Ky = 0.5f*(Zm.x - Zf.x);
            // P = Q * conj(K)
            float2 P = make_float2(Qx*Kx + Qy*Ky, Qy*Kx - Qx*Ky);
            acc[f] = cadd(acc[f], P);
        }
        __syncthreads();
    }
    float2* outp = Spart + ((((size_t)b) << 5) + g) * 1024;
    for (int f = tid; f < 1024; f += 256) outp[f] = acc[f];
}

// mean_corr[b,tau] = Re(ifft(sum_g Spart))[tau] / 512
__global__ __launch_bounds__(256)
void corr_ifft_kernel(const float2* __restrict__ Spart, float* __restrict__ corr)
{
    __shared__ float2 z[1024];
    __shared__ float2 tw[512];
    int tid = threadIdx.x;
    int b = blockIdx.x;

    for (int i = tid; i < 512; i += 256) {
        float s, c;
        sincosf(6.283185307179586f * (float)i / 1024.f, &s, &c);
        tw[i] = make_float2(c, s);
    }
    __syncthreads();
    for (int t = tid; t < 1024; t += 256) {
        float2 s = make_float2(0.f, 0.f);
        const float2* sp = Spart + ((((size_t)b) << 5) * 1024) + t;
        for (int g2 = 0; g2 < 32; g2++) s = cadd(s, sp[(size_t)g2 << 10]);
        z[__brev((unsigned)t) >> 22] = s;
    }
    __syncthreads();
    fft1024(z, tw);
    const float scale = 1.f / (1024.f * 512.f);
    for (int t = tid; t < 1024; t += 256)
        corr[(b << 10) + t] = z[t].x * scale;
}

// top-6 + softmax per batch
__global__ __launch_bounds__(256)
void topk_kernel(const float* __restrict__ corr, float* __restrict__ tcw, int* __restrict__ dly)
{
    int b = blockIdx.x, t = threadIdx.x;
    __shared__ float vals[1024];
    __shared__ float rv[256];
    __shared__ int   ri[256];
    __shared__ float wv[TOPK_];
    __shared__ int   wi[TOPK_];
    for (int i = t; i < 1024; i += 256) vals[i] = corr[(b << 10) + i];
    __syncthreads();
    for (int kk = 0; kk < TOPK_; kk++) {
        float bm = -INFINITY; int bi = 0x7fffffff;
        for (int i = t; i < 1024; i += 256) {
            float v = vals[i];
            if (v > bm || (v == bm && i < bi)) { bm = v; bi = i; }
        }
        rv[t] = bm; ri[t] = bi;
        __syncthreads();
        for (int s = 128; s > 0; s >>= 1) {
            if (t < s) {
                if (rv[t+s] > rv[t] || (rv[t+s] == rv[t] && ri[t+s] < ri[t])) {
                    rv[t] = rv[t+s]; ri[t] = ri[t+s];
                }
            }
            __syncthreads();
        }
        if (t == 0) { wv[kk] = rv[0]; wi[kk] = ri[0]; vals[ri[0]] = -INFINITY; }
        __syncthreads();
    }
    if (t == 0) {
        float m = wv[0];
        for (int kk = 1; kk < TOPK_; kk++) m = fmaxf(m, wv[kk]);
        float e[TOPK_], s = 0.f;
        for (int kk = 0; kk < TOPK_; kk++) { e[kk] = expf(wv[kk] - m); s += e[kk]; }
        float inv = 1.f / s;
        for (int kk = 0; kk < TOPK_; kk++) {
            tcw[b*TOPK_ + kk] = e[kk] * inv;
            dly[b*TOPK_ + kk] = wi[kk];
        }
    }
}

// a[b,l,:] = sum_k tc_k * v[b,(l+delay_k)%L,:]
__global__ __launch_bounds__(128)
void agg_kernel(const float* __restrict__ v, const float* __restrict__ tcw,
                const int* __restrict__ dly, float* __restrict__ outp)
{
    int bl = blockIdx.x;
    int b = bl >> 10, l = bl & 1023;
    __shared__ float w[TOPK_];
    __shared__ int   dd[TOPK_];
    if (threadIdx.x < TOPK_) {
        w[threadIdx.x]  = tcw[b*TOPK_ + threadIdx.x];
        dd[threadIdx.x] = dly[b*TOPK_ + threadIdx.x];
    }
    __syncthreads();
    int c = threadIdx.x << 2;
    float4 acc = make_float4(0.f, 0.f, 0.f, 0.f);
#pragma unroll
    for (int kk = 0; kk < TOPK_; kk++) {
        int row = (l + dd[kk]) & 1023;
        float4 vv = *(const float4*)(v + (((((size_t)b) << 10) + row) << 9) + c);
        acc.x = fmaf(w[kk], vv.x, acc.x);
        acc.y = fmaf(w[kk], vv.y, acc.y);
        acc.z = fmaf(w[kk], vv.z, acc.z);
        acc.w = fmaf(w[kk], vv.w, acc.w);
    }
    *(float4*)(outp + (((size_t)bl) << 9) + c) = acc;
}

// out = s - movavg25(s), s = in1 + in2, edge-replicated (clamped) window
__global__ __launch_bounds__(256)
void decomp_kernel(const float* __restrict__ in1, const float* __restrict__ in2,
                   float* __restrict__ outp)
{
    __shared__ float s[152][64];
    int b = blockIdx.x, lt = blockIdx.y, dt = blockIdx.z;
    int l0 = lt << 7, d0 = dt << 6;
    int tid = threadIdx.x;
    for (int i = tid; i < 152*64; i += 256) {
        int r = i >> 6, d = i & 63;
        int l = l0 - 12 + r;
        l = l < 0 ? 0 : (l > 1023 ? 1023 : l);
        size_t gi = (((((size_t)b) << 10) + l) << 9) + d0 + d;
        s[r][d] = in1[gi] + in2[gi];
    }
    __syncthreads();
    int d = tid & 63, ch = tid >> 6;
    int lb = ch << 5;
    float sum = 0.f;
#pragma unroll
    for (int j = 0; j < 25; j++) sum += s[lb + j][d];
    for (int i = 0; i < 32; i++) {
        size_t gi = (((((size_t)b) << 10) + (l0 + lb + i)) << 9) + d0 + d;
        outp[gi] = s[lb + 12 + i][d] - sum * (1.f/25.f);
        if (i != 31) sum += s[lb + 25 + i][d] - s[lb + i][d];
    }
}

// layernorm (over D) with gamma/beta
__global__ __launch_bounds__(128)
void ln_kernel(const float* __restrict__ h, const float* __restrict__ gam,
               const float* __restrict__ bet, float* __restrict__ hn)
{
    int row = blockIdx.x;
    int t = threadIdx.x;
    const float4 x = *(const float4*)(h + (((size_t)row) << 9) + (t << 2));
    float s1 = x.x + x.y + x.z + x.w;
    float s2 = x.x*x.x + x.y*x.y + x.z*x.z + x.w*x.w;
#pragma unroll
    for (int o = 16; o > 0; o >>= 1) {
        s1 += __shfl_xor_sync(0xffffffffu, s1, o);
        s2 += __shfl_xor_sync(0xffffffffu, s2, o);
    }
    __shared__ float a1[4], a2[4];
    if ((t & 31) == 0) { a1[t >> 5] = s1; a2[t >> 5] = s2; }
    __syncthreads();
    s1 = a1[0] + a1[1] + a1[2] + a1[3];
    s2 = a2[0] + a2[1] + a2[2] + a2[3];
    float mu  = s1 * (1.f/512.f);
    float var = s2 * (1.f/512.f) - mu*mu;
    float rs  = rsqrtf(var + 1e-5f);
    int c = t << 2;
    float4 o4;
    o4.x = (x.x - mu)*rs*gam[c+0] + bet[c+0];
    o4.y = (x.y - mu)*rs*gam[c+1] + bet[c+1];
    o4.z = (x.z - mu)*rs*gam[c+2] + bet[c+2];
    o4.w = (x.w - mu)*rs*gam[c+3] + bet[c+3];
    *(float4*)(hn + (((size_t)row) << 9) + c) = o4;
}

// per-(b,d) mean over L of hn
__global__ __launch_bounds__(128)
void colmean_kernel(const float* __restrict__ hn, float* __restrict__ cm)
{
    int b = blockIdx.x;
    int d = blockIdx.y * 128 + threadIdx.x;
    float s = 0.f;
    const float* p = hn + ((((size_t)b) << 10) << 9) + d;
    for (int l = 0; l < 1024; l++) s += p[((size_t)l) << 9];
    cm[(b << 9) + d] = s * (1.f/1024.f);
}

// cb[b,n] = colmean[b,:] @ proj_w[:,n]
__global__ __launch_bounds__(64)
void cbias_kernel(const float* __restrict__ cm, const float* __restrict__ pw,
                  float* __restrict__ cb)
{
    int b = blockIdx.x, n = threadIdx.x;
    float s = 0.f;
    for (int d2 = 0; d2 < 512; d2++) s = fmaf(cm[(b << 9) + d2], pw[d2*64 + n], s);
    cb[(b << 6) + n] = s;
}

// out[b,l,n] -= cb[b,n]
__global__ void sub_kernel(float* __restrict__ outp, const float* __restrict__ cb)
{
    int i = blockIdx.x * blockDim.x + threadIdx.x;
    if (i >= MROWS*64) return;
    outp[i] -= cb[((i >> 16) << 6) + (i & 63)];
}

// ---------------- host launcher ----------------
extern "C" void kernel_launch(void* const* d_in, const int* in_sizes, int n_in,
                              void* d_out, int out_size)
{
    const float* x       = (const float*)d_in[0];
    const float* embed_w = (const float*)d_in[1];
    const float* wq = (const float*)d_in[2];  const float* bq = (const float*)d_in[3];
    const float* wk = (const float*)d_in[4];  const float* bk = (const float*)d_in[5];
    const float* wv = (const float*)d_in[6];  const float* bv = (const float*)d_in[7];
    const float* wo = (const float*)d_in[8];  const float* bo = (const float*)d_in[9];
    const float* w1 = (const float*)d_in[10]; const float* w2 = (const float*)d_in[11];
    const float* ln_g = (const float*)d_in[12]; const float* ln_b = (const float*)d_in[13];
    const float* pw = (const float*)d_in[14]; const float* pb = (const float*)d_in[15];
    float* outp = (float*)d_out;
    (void)in_sizes; (void)n_in; (void)out_size;

    float *h, *h2, *q, *k, *v, *a, *t, *ffn, *xc, *corr, *tcw, *cm, *cb;
    float2* sp; int* dly;
    cudaGetSymbolAddress((void**)&h,   g_h);
    cudaGetSymbolAddress((void**)&h2,  g_h2);
    cudaGetSymbolAddress((void**)&q,   g_q);
    cudaGetSymbolAddress((void**)&k,   g_k);
    cudaGetSymbolAddress((void**)&v,   g_v);
    cudaGetSymbolAddress((void**)&a,   g_a);
    cudaGetSymbolAddress((void**)&t,   g_t);
    cudaGetSymbolAddress((void**)&ffn, g_ffn);
    cudaGetSymbolAddress((void**)&xc,  g_xcat);
    cudaGetSymbolAddress((void**)&sp,  g_Spart);
    cudaGetSymbolAddress((void**)&corr,g_corr);
    cudaGetSymbolAddress((void**)&tcw, g_tcw);
    cudaGetSymbolAddress((void**)&dly, g_dly);
    cudaGetSymbolAddress((void**)&cm,  g_cm);
    cudaGetSymbolAddress((void**)&cb,  g_cb);

    dim3 gN512(4, MROWS/128);
    dim3 gN2048(16, MROWS/128);
    dim3 gN64(1, MROWS/128);

    // token embedding (circular conv1d k=3 as gather + GEMM)
    xcat_kernel<<<(MROWS*192 + 255)/256, 256>>>(x, xc);
    sgemm_kernel<0><<<gN512, 256>>>(xc, embed_w, nullptr, h, MROWS, 512, 192);

    for (int l = 0; l < NL_; l++) {
        const float* wql = wq + (size_t)l*D_*D_;  const float* bql = bq + l*D_;
        const float* wkl = wk + (size_t)l*D_*D_;  const float* bkl = bk + l*D_;
        const float* wvl = wv + (size_t)l*D_*D_;  const float* bvl = bv + l*D_;
        const float* wol = wo + (size_t)l*D_*D_;  const float* bol = bo + l*D_;
        const float* w1l = w1 + (size_t)l*D_*DFF_;
        const float* w2l = w2 + (size_t)l*DFF_*D_;

        sgemm_kernel<0><<<gN512, 256>>>(h, wql, bql, q, MROWS, 512, 512);
        sgemm_kernel<0><<<gN512, 256>>>(h, wkl, bkl, k, MROWS, 512, 512);
        sgemm_kernel<0><<<gN512, 256>>>(h, wvl, bvl, v, MROWS, 512, 512);

        corr_fft_kernel <<<dim3(B_, 32), 256>>>(q, k, sp);
        corr_ifft_kernel<<<B_, 256>>>(sp, corr);
        topk_kernel     <<<B_, 256>>>(corr, tcw, dly);
        agg_kernel      <<<MROWS, 128>>>(v, tcw, dly, a);

        sgemm_kernel<0><<<gN512, 256>>>(a, wol, bol, t, MROWS, 512, 512);
        decomp_kernel<<<dim3(B_, 8, 8), 256>>>(h, t, h2);

        sgemm_kernel<1><<<gN2048, 256>>>(h2, w1l, nullptr, ffn, MROWS, 2048, 512);
        sgemm_kernel<0><<<gN512, 256>>>(ffn, w2l, nullptr, t, MROWS, 512, 2048);
        decomp_kernel<<<dim3(B_, 8, 8), 256>>>(h2, t, h);
    }

    // final my_Layernorm + time-mean subtraction + projection
    ln_kernel<<<MROWS, 128>>>(h, ln_g, ln_b, q);            // hn -> g_q
    colmean_kernel<<<dim3(B_, 4), 128>>>(q, cm);
    cbias_kernel<<<B_, 64>>>(cm, pw, cb);
    sgemm_kernel<0><<<gN64, 256>>>(q, pw, pb, outp, MROWS, 64, 512);
    sub_kernel<<<(MROWS*64 + 255)/256, 256>>>(outp, cb);
}

// round 9
// speedup vs baseline: 3.3769x; 3.3664x over previous
#include <cuda_runtime.h>
#include <math.h>
#include <stdint.h>

#define B_    32
#define L_    1024
#define CIN_  64
#define D_    512
#define DFF_  2048
#define NL_   3
#define TOPK_ 6
#define MROWS (B_*L_)   /* 32768 */

// ---------------- scratch (device globals; allocation-free) ----------------
__device__ float  g_h  [MROWS*D_];
__device__ float  g_h2 [MROWS*D_];
__device__ float  g_q  [MROWS*D_];
__device__ float  g_k  [MROWS*D_];
__device__ float  g_v  [MROWS*D_];
__device__ float  g_a  [MROWS*D_];
__device__ float  g_t  [MROWS*D_];
__device__ float  g_ffn[MROWS*DFF_];
__device__ float  g_xcat[MROWS*3*CIN_];
__device__ float2 g_Spart[B_*32*L_];
__device__ float  g_corr[B_*L_];
__device__ float  g_tcw [B_*TOPK_];
__device__ int    g_dly [B_*TOPK_];
__device__ float  g_cm  [B_*D_];
__device__ float  g_cb  [B_*CIN_];
// transposed (N,K) weights, rounded to tf32
__device__ float  g_wtq[NL_*D_*D_];
__device__ float  g_wtk[NL_*D_*D_];
__device__ float  g_wtv[NL_*D_*D_];
__device__ float  g_wto[NL_*D_*D_];
__device__ float  g_wt1[NL_*DFF_*D_];   // (2048,512) per layer
__device__ float  g_wt2[NL_*D_*DFF_];   // (512,2048) per layer
__device__ float  g_wte[D_*192];        // (512,192)
__device__ float  g_wtp[128*D_];        // (64,512) padded to 128 rows

// ---------------- helpers ----------------
__device__ __forceinline__ float rtf32(float x) {
    uint32_t b = __float_as_uint(x);
    b = (b + 0x1000u) & 0xffffe000u;      // round-to-nearest tf32, zero low bits
    return __uint_as_float(b);
}
__device__ __forceinline__ float2 cadd(float2 a, float2 b){ return make_float2(a.x+b.x, a.y+b.y); }
__device__ __forceinline__ float2 csub(float2 a, float2 b){ return make_float2(a.x-b.x, a.y-b.y); }
__device__ __forceinline__ float2 cmul(float2 a, float2 b){ return make_float2(a.x*b.x-a.y*b.y, a.x*b.y+a.y*b.x); }

__device__ __forceinline__ uint32_t smem_u32(const void* p){
    uint32_t a;
    asm("{ .reg .u64 t; cvta.to.shared.u64 t, %1; cvt.u32.u64 %0, t; }" : "=r"(a) : "l"(p));
    return a;
}
__device__ __forceinline__ void cp16(uint32_t s, const void* g){
    asm volatile("cp.async.cg.shared.global [%0], [%1], 16;" :: "r"(s), "l"(g));
}
__device__ __forceinline__ void ldsm4(uint32_t* r, uint32_t addr){
    asm volatile("ldmatrix.sync.aligned.m8n8.x4.shared.b16 {%0,%1,%2,%3}, [%4];"
        : "=r"(r[0]),"=r"(r[1]),"=r"(r[2]),"=r"(r[3]) : "r"(addr));
}
#define MMA_TF32(d, a, b0, b1) \
    asm volatile("mma.sync.aligned.m16n8k8.row.col.f32.tf32.tf32.f32 " \
        "{%0,%1,%2,%3},{%4,%5,%6,%7},{%8,%9},{%0,%1,%2,%3};" \
        : "+f"((d)[0]),"+f"((d)[1]),"+f"((d)[2]),"+f"((d)[3]) \
        : "r"((a)[0]),"r"((a)[1]),"r"((a)[2]),"r"((a)[3]), "r"(b0),"r"(b1))

// ---------------- weight transpose (K,N)->(Npad,K), rounded to tf32 ----------------
__global__ void transpose_kernel(const float* __restrict__ in, float* __restrict__ out,
                                 int K, int N, int Npad)
{
    __shared__ float t[32][33];
    int kb = blockIdx.y << 5, nb = blockIdx.x << 5;
    int x = threadIdx.x, y = threadIdx.y;     // 32 x 8
#pragma unroll
    for (int i = 0; i < 32; i += 8) {
        int k = kb + y + i, n = nb + x;
        t[y + i][x] = (k < K && n < N) ? in[(size_t)k * N + n] : 0.f;
    }
    __syncthreads();
#pragma unroll
    for (int i = 0; i < 32; i += 8) {
        int n = nb + y + i, k = kb + x;
        if (n < Npad && k < K) out[(size_t)n * K + k] = rtf32(t[x][y + i]);
    }
}

// ---------------- circular-pad gather for token embedding ----------------
__global__ void xcat_kernel(const float* __restrict__ x, float* __restrict__ xc)
{
    int idx = blockIdx.x*blockDim.x + threadIdx.x;
    if (idx >= MROWS*192) return;
    int row = idx / 192, cc = idx % 192;
    int j = cc >> 6, c = cc & 63;
    int b = row >> 10, l = row & 1023;
    int ls = (l + j + 1023) & 1023;
    xc[idx] = rtf32(x[((((size_t)b)<<10) + ls)*64 + c]);
}

// ---------------- tf32 mma.sync GEMM: C[M,N] = A[M,K] * WT[N,K]^T ----------------
// BM=128, BN=128, BK=32; 8 warps of 64x32; 3-stage cp.async pipeline.
// A, WT already tf32-rounded. WT padded to 128-row multiples.
template<int GELU, int ROUND>
__global__ __launch_bounds__(256)
void tgemm(const float* __restrict__ A, const float* __restrict__ WT,
           const float* __restrict__ bias, float* __restrict__ C, int K, int N)
{
    constexpr int STG_F = 8192;                 // floats per stage: A 4096 + B 4096
    extern __shared__ float sm[];
    int tid = threadIdx.x;
    int lane = tid & 31, wid = tid >> 5;
    int wm = wid & 1, wn = wid >> 1;            // warp grid 2(m) x 4(n)
    int bx = blockIdx.x, by = blockIdx.y;

    const float* Ab = A  + (size_t)(by * 128) * (size_t)K;
    const float* Bb = WT + (size_t)(bx * 128) * (size_t)K;
    const int nck = K >> 5;

    uint32_t sbase = smem_u32(sm);

    auto load = [&](int ck, int s){
        const float* ap = Ab + ck * 32;
        const float* bp = Bb + ck * 32;
        uint32_t st  = sbase + (uint32_t)s * (STG_F * 4);
        uint32_t st2 = st + 4096 * 4;
#pragma unroll
        for (int i = 0; i < 4; i++) {
            int t = tid + i*256;
            int row = t >> 3, ch = t & 7;
            uint32_t off = (uint32_t)((row << 7) + ((ch ^ (row & 7)) << 4));
            cp16(st + off, ap + (size_t)row*K + (ch << 2));
        }
#pragma unroll
        for (int i = 0; i < 4; i++) {
            int t = tid + i*256;
            int row = t >> 3, ch = t & 7;
            uint32_t off = (uint32_t)((row << 7) + ((ch ^ (row & 7)) << 4));
            cp16(st2 + off, bp + (size_t)row*K + (ch << 2));
        }
        asm volatile("cp.async.commit_group;" ::: "memory");
    };

    float acc[4][4][4];
#pragma unroll
    for (int mt = 0; mt < 4; mt++)
#pragma unroll
        for (int nt = 0; nt < 4; nt++)
#pragma unroll
            for (int j = 0; j < 4; j++) acc[mt][nt][j] = 0.f;

    // per-thread ldmatrix row indices (within CTA tile)
    int g = lane >> 3, r8 = lane & 7;
    int rA[4], rB[2];
#pragma unroll
    for (int mt = 0; mt < 4; mt++) rA[mt] = wm*64 + mt*16 + (g & 1)*8 + r8;
#pragma unroll
    for (int p = 0; p < 2; p++)    rB[p]  = wn*32 + p*16 + (g >> 1)*8 + r8;
    int chA = g >> 1;     // 0/1: lo/hi 16B chunk of the k-step
    int chB = g & 1;

    load(0, 0); load(1, 1); load(2, 2);
    int s = 0;

    for (int ck = 0; ck < nck; ck++) {
        asm volatile("cp.async.wait_group 2;" ::: "memory");
        __syncthreads();
        uint32_t sa = sbase + (uint32_t)s * (STG_F * 4);
        uint32_t sb = sa + 4096 * 4;
#pragma unroll
        for (int kk = 0; kk < 4; kk++) {
            uint32_t af[4][4], bf[2][4];
#pragma unroll
            for (int mt = 0; mt < 4; mt++) {
                int ch = 2*kk + chA;
                uint32_t off = (uint32_t)((rA[mt] << 7) + ((ch ^ (rA[mt] & 7)) << 4));
                ldsm4(af[mt], sa + off);
            }
#pragma unroll
            for (int p = 0; p < 2; p++) {
                int ch = 2*kk + chB;
                uint32_t off = (uint32_t)((rB[p] << 7) + ((ch ^ (rB[p] & 7)) << 4));
                ldsm4(bf[p], sb + off);
            }
#pragma unroll
            for (int mt = 0; mt < 4; mt++)
#pragma unroll
                for (int nt = 0; nt < 4; nt++) {
                    int p = nt >> 1, q = nt & 1;
                    MMA_TF32(acc[mt][nt], af[mt], bf[p][2*q], bf[p][2*q+1]);
                }
        }
        __syncthreads();
        if (ck + 3 < nck) load(ck + 3, s);
        else asm volatile("cp.async.commit_group;" ::: "memory");
        s = (s == 2) ? 0 : s + 1;
    }

    // epilogue
#pragma unroll
    for (int mt = 0; mt < 4; mt++) {
        int r0 = by*128 + wm*64 + mt*16 + (lane >> 2);
        float* row0 = C + (size_t)r0 * (size_t)N;
        float* row1 = row0 + ((size_t)N << 3);   // r0 + 8
#pragma unroll
        for (int nt = 0; nt < 4; nt++) {
            int c = bx*128 + wn*32 + nt*8 + ((lane & 3) << 1);
            if (c < N) {
                float v0 = acc[mt][nt][0], v1 = acc[mt][nt][1];
                float v2 = acc[mt][nt][2], v3 = acc[mt][nt][3];
                if (bias != nullptr) {
                    float b0c = bias[c], b1c = bias[c+1];
                    v0 += b0c; v1 += b1c; v2 += b0c; v3 += b1c;
                }
                if (GELU) {
                    v0 = 0.5f*v0*(1.f + erff(v0*0.7071067811865475f));
                    v1 = 0.5f*v1*(1.f + erff(v1*0.7071067811865475f));
                    v2 = 0.5f*v2*(1.f + erff(v2*0.7071067811865475f));
                    v3 = 0.5f*v3*(1.f + erff(v3*0.7071067811865475f));
                }
                if (ROUND) { v0 = rtf32(v0); v1 = rtf32(v1); v2 = rtf32(v2); v3 = rtf32(v3); }
                *(float2*)(row0 + c) = make_float2(v0, v1);
                *(float2*)(row1 + c) = make_float2(v2, v3);
            }
        }
    }
}

// ---------------- length-1024 in-place radix-2 FFT (input bit-reversed) ----------------
__device__ void fft1024(float2* z, const float2* tw)
{
    int tid = threadIdx.x;   // blockDim == 256
    for (int half = 1; half < 1024; half <<= 1) {
        int step = 512 / half;
#pragma unroll 2
        for (int idx = tid; idx < 512; idx += 256) {
            int j = idx & (half - 1);
            int base = (idx & ~(half - 1)) << 1;
            float2 w = tw[j * step];
            float2 u = z[base + j];
            float2 t = cmul(w, z[base + j + half]);
            z[base + j]        = cadd(u, t);
            z[base + j + half] = csub(u, t);
        }
        __syncthreads();
    }
}

__global__ __launch_bounds__(256)
void corr_fft_kernel(const float* __restrict__ q, const float* __restrict__ k,
                     float2* __restrict__ Spart)
{
    __shared__ float2 z[1024];
    __shared__ float2 acc[1024];
    __shared__ float2 tw[512];
    int tid = threadIdx.x;
    int b = blockIdx.x, g = blockIdx.y;

    for (int i = tid; i < 512; i += 256) {
        float s, c;
        sincosf(-6.283185307179586f * (float)i / 1024.f, &s, &c);
        tw[i] = make_float2(c, s);
    }
    for (int i = tid; i < 1024; i += 256) acc[i] = make_float2(0.f, 0.f);
    __syncthreads();

    const float* qb = q + (((size_t)b) << 10) * 512;
    const float* kb = k + (((size_t)b) << 10) * 512;

    for (int dd = 0; dd < 16; dd++) {
        int d = (g << 4) + dd;
        for (int t = tid; t < 1024; t += 256) {
            int r = __brev((unsigned)t) >> 22;
            z[r] = make_float2(qb[(((size_t)t) << 9) + d], kb[(((size_t)t) << 9) + d]);
        }
        __syncthreads();
        fft1024(z, tw);
        for (int f = tid; f < 1024; f += 256) {
            float2 Zf = z[f];
            float2 Zm = z[(1024 - f) & 1023];
            float Qx = 0.5f*(Zf.x + Zm.x), Qy = 0.5f*(Zf.y - Zm.y);
            float Kx = 0.5f*(Zf.y + Zm.y), Ky = 0.5f*(Zm.x - Zf.x);
            float2 P = make_float2(Qx*Kx + Qy*Ky, Qy*Kx - Qx*Ky);
            acc[f] = cadd(acc[f], P);
        }
        __syncthreads();
    }
    float2* outp = Spart + ((((size_t)b) << 5) + g) * 1024;
    for (int f = tid; f < 1024; f += 256) outp[f] = acc[f];
}

__global__ __launch_bounds__(256)
void corr_ifft_kernel(const float2* __restrict__ Spart, float* __restrict__ corr)
{
    __shared__ float2 z[1024];
    __shared__ float2 tw[512];
    int tid = threadIdx.x;
    int b = blockIdx.x;

    for (int i = tid; i < 512; i += 256) {
        float s, c;
        sincosf(6.283185307179586f * (float)i / 1024.f, &s, &c);
        tw[i] = make_float2(c, s);
    }
    __syncthreads();
    for (int t = tid; t < 1024; t += 256) {
        float2 s = make_float2(0.f, 0.f);
        const float2* sp = Spart + ((((size_t)b) << 5) * 1024) + t;
        for (int g2 = 0; g2 < 32; g2++) s = cadd(s, sp[(size_t)g2 << 10]);
        z[__brev((unsigned)t) >> 22] = s;
    }
    __syncthreads();
    fft1024(z, tw);
    const float scale = 1.f / (1024.f * 512.f);
    for (int t = tid; t < 1024; t += 256)
        corr[(b << 10) + t] = z[t].x * scale;
}

__global__ __launch_bounds__(256)
void topk_kernel(const float* __restrict__ corr, float* __restrict__ tcw, int* __restrict__ dly)
{
    int b = blockIdx.x, t = threadIdx.x;
    __shared__ float vals[1024];
    __shared__ float rv[256];
    __shared__ int   ri[256];
    __shared__ float wv[TOPK_];
    __shared__ int   wi[TOPK_];
    for (int i = t; i < 1024; i += 256) vals[i] = corr[(b << 10) + i];
    __syncthreads();
    for (int kk = 0; kk < TOPK_; kk++) {
        float bm = -INFINITY; int bi = 0x7fffffff;
        for (int i = t; i < 1024; i += 256) {
            float v = vals[i];
            if (v > bm || (v == bm && i < bi)) { bm = v; bi = i; }
        }
        rv[t] = bm; ri[t] = bi;
        __syncthreads();
        for (int s = 128; s > 0; s >>= 1) {
            if (t < s) {
                if (rv[t+s] > rv[t] || (rv[t+s] == rv[t] && ri[t+s] < ri[t])) {
                    rv[t] = rv[t+s]; ri[t] = ri[t+s];
                }
            }
            __syncthreads();
        }
        if (t == 0) { wv[kk] = rv[0]; wi[kk] = ri[0]; vals[ri[0]] = -INFINITY; }
        __syncthreads();
    }
    if (t == 0) {
        float m = wv[0];
        for (int kk = 1; kk < TOPK_; kk++) m = fmaxf(m, wv[kk]);
        float e[TOPK_], s = 0.f;
        for (int kk = 0; kk < TOPK_; kk++) { e[kk] = expf(wv[kk] - m); s += e[kk]; }
        float inv = 1.f / s;
        for (int kk = 0; kk < TOPK_; kk++) {
            tcw[b*TOPK_ + kk] = e[kk] * inv;
            dly[b*TOPK_ + kk] = wi[kk];
        }
    }
}

__global__ __launch_bounds__(128)
void agg_kernel(const float* __restrict__ v, const float* __restrict__ tcw,
                const int* __restrict__ dly, float* __restrict__ outp)
{
    int bl = blockIdx.x;
    int b = bl >> 10, l = bl & 1023;
    __shared__ float w[TOPK_];
    __shared__ int   dd[TOPK_];
    if (threadIdx.x < TOPK_) {
        w[threadIdx.x]  = tcw[b*TOPK_ + threadIdx.x];
        dd[threadIdx.x] = dly[b*TOPK_ + threadIdx.x];
    }
    __syncthreads();
    int c = threadIdx.x << 2;
    float4 acc = make_float4(0.f, 0.f, 0.f, 0.f);
#pragma unroll
    for (int kk = 0; kk < TOPK_; kk++) {
        int row = (l + dd[kk]) & 1023;
        float4 vv = *(const float4*)(v + (((((size_t)b) << 10) + row) << 9) + c);
        acc.x = fmaf(w[kk], vv.x, acc.x);
        acc.y = fmaf(w[kk], vv.y, acc.y);
        acc.z = fmaf(w[kk], vv.z, acc.z);
        acc.w = fmaf(w[kk], vv.w, acc.w);
    }
    acc.x = rtf32(acc.x); acc.y = rtf32(acc.y); acc.z = rtf32(acc.z); acc.w = rtf32(acc.w);
    *(float4*)(outp + (((size_t)bl) << 9) + c) = acc;
}

__global__ __launch_bounds__(256)
void decomp_kernel(const float* __restrict__ in1, const float* __restrict__ in2,
                   float* __restrict__ outp)
{
    __shared__ float s[152][64];
    int b = blockIdx.x, lt = blockIdx.y, dt = blockIdx.z;
    int l0 = lt << 7, d0 = dt << 6;
    int tid = threadIdx.x;
    for (int i = tid; i < 152*64; i += 256) {
        int r = i >> 6, d = i & 63;
        int l = l0 - 12 + r;
        l = l < 0 ? 0 : (l > 1023 ? 1023 : l);
        size_t gi = (((((size_t)b) << 10) + l) << 9) + d0 + d;
        s[r][d] = in1[gi] + in2[gi];
    }
    __syncthreads();
    int d = tid & 63, ch = tid >> 6;
    int lb = ch << 5;
    float sum = 0.f;
#pragma unroll
    for (int j = 0; j < 25; j++) sum += s[lb + j][d];
    for (int i = 0; i < 32; i++) {
        size_t gi = (((((size_t)b) << 10) + (l0 + lb + i)) << 9) + d0 + d;
        outp[gi] = rtf32(s[lb + 12 + i][d] - sum * (1.f/25.f));
        if (i != 31) sum += s[lb + 25 + i][d] - s[lb + i][d];
    }
}

__global__ __launch_bounds__(128)
void ln_kernel(const float* __restrict__ h, const float* __restrict__ gam,
               const float* __restrict__ bet, float* __restrict__ hn)
{
    int row = blockIdx.x;
    int t = threadIdx.x;
    const float4 x = *(const float4*)(h + (((size_t)row) << 9) + (t << 2));
    float s1 = x.x + x.y + x.z + x.w;
    float s2 = x.x*x.x + x.y*x.y + x.z*x.z + x.w*x.w;
#pragma unroll
    for (int o = 16; o > 0; o >>= 1) {
        s1 += __shfl_xor_sync(0xffffffffu, s1, o);
        s2 += __shfl_xor_sync(0xffffffffu, s2, o);
    }
    __shared__ float a1[4], a2[4];
    if ((t & 31) == 0) { a1[t >> 5] = s1; a2[t >> 5] = s2; }
    __syncthreads();
    s1 = a1[0] + a1[1] + a1[2] + a1[3];
    s2 = a2[0] + a2[1] + a2[2] + a2[3];
    float mu  = s1 * (1.f/512.f);
    float var = s2 * (1.f/512.f) - mu*mu;
    float rs  = rsqrtf(var + 1e-5f);
    int c = t << 2;
    float4 o4;
    o4.x = rtf32((x.x - mu)*rs*gam[c+0] + bet[c+0]);
    o4.y = rtf32((x.y - mu)*rs*gam[c+1] + bet[c+1]);
    o4.z = rtf32((x.z - mu)*rs*gam[c+2] + bet[c+2]);
    o4.w = rtf32((x.w - mu)*rs*gam[c+3] + bet[c+3]);
    *(float4*)(hn + (((size_t)row) << 9) + c) = o4;
}

__global__ __launch_bounds__(128)
void colmean_kernel(const float* __restrict__ hn, float* __restrict__ cm)
{
    int b = blockIdx.x;
    int d = blockIdx.y * 128 + threadIdx.x;
    float s = 0.f;
    const float* p = hn + ((((size_t)b) << 10) << 9) + d;
    for (int l = 0; l < 1024; l++) s += p[((size_t)l) << 9];
    cm[(b << 9) + d] = s * (1.f/1024.f);
}

__global__ __launch_bounds__(64)
void cbias_kernel(const float* __restrict__ cm, const float* __restrict__ pw,
                  float* __restrict__ cb)
{
    int b = blockIdx.x, n = threadIdx.x;
    float s = 0.f;
    for (int d2 = 0; d2 < 512; d2++) s = fmaf(cm[(b << 9) + d2], rtf32(pw[d2*64 + n]), s);
    cb[(b << 6) + n] = s;
}

__global__ void sub_kernel(float* __restrict__ outp, const float* __restrict__ cb)
{
    int i = blockIdx.x * blockDim.x + threadIdx.x;
    if (i >= MROWS*64) return;
    outp[i] -= cb[((i >> 16) << 6) + (i & 63)];
}

// ---------------- host launcher ----------------
extern "C" void kernel_launch(void* const* d_in, const int* in_sizes, int n_in,
                              void* d_out, int out_size)
{
    const float* x       = (const float*)d_in[0];
    const float* embed_w = (const float*)d_in[1];
    const float* wq = (const float*)d_in[2];  const float* bq = (const float*)d_in[3];
    const float* wk = (const float*)d_in[4];  const float* bk = (const float*)d_in[5];
    const float* wv = (const float*)d_in[6];  const float* bv = (const float*)d_in[7];
    const float* wo = (const float*)d_in[8];  const float* bo = (const float*)d_in[9];
    const float* w1 = (const float*)d_in[10]; const float* w2 = (const float*)d_in[11];
    const float* ln_g = (const float*)d_in[12]; const float* ln_b = (const float*)d_in[13];
    const float* pw = (const float*)d_in[14]; const float* pb = (const float*)d_in[15];
    float* outp = (float*)d_out;
    (void)in_sizes; (void)n_in; (void)out_size;

    float *h, *h2, *q, *k, *v, *a, *t, *ffn, *xc, *corr, *tcw, *cm, *cb;
    float *wtq, *wtk, *wtv, *wto, *wt1, *wt2, *wte, *wtp;
    float2* sp; int* dly;
    cudaGetSymbolAddress((void**)&h,   g_h);
    cudaGetSymbolAddress((void**)&h2,  g_h2);
    cudaGetSymbolAddress((void**)&q,   g_q);
    cudaGetSymbolAddress((void**)&k,   g_k);
    cudaGetSymbolAddress((void**)&v,   g_v);
    cudaGetSymbolAddress((void**)&a,   g_a);
    cudaGetSymbolAddress((void**)&t,   g_t);
    cudaGetSymbolAddress((void**)&ffn, g_ffn);
    cudaGetSymbolAddress((void**)&xc,  g_xcat);
    cudaGetSymbolAddress((void**)&sp,  g_Spart);
    cudaGetSymbolAddress((void**)&corr,g_corr);
    cudaGetSymbolAddress((void**)&tcw, g_tcw);
    cudaGetSymbolAddress((void**)&dly, g_dly);
    cudaGetSymbolAddress((void**)&cm,  g_cm);
    cudaGetSymbolAddress((void**)&cb,  g_cb);
    cudaGetSymbolAddress((void**)&wtq, g_wtq);
    cudaGetSymbolAddress((void**)&wtk, g_wtk);
    cudaGetSymbolAddress((void**)&wtv, g_wtv);
    cudaGetSymbolAddress((void**)&wto, g_wto);
    cudaGetSymbolAddress((void**)&wt1, g_wt1);
    cudaGetSymbolAddress((void**)&wt2, g_wt2);
    cudaGetSymbolAddress((void**)&wte, g_wte);
    cudaGetSymbolAddress((void**)&wtp, g_wtp);

    const int SMB = 3 * 8192 * 4;   // 98304 bytes
    cudaFuncSetAttribute(tgemm<0,1>, cudaFuncAttributeMaxDynamicSharedMemorySize, SMB);
    cudaFuncSetAttribute(tgemm<1,1>, cudaFuncAttributeMaxDynamicSharedMemorySize, SMB);
    cudaFuncSetAttribute(tgemm<0,0>, cudaFuncAttributeMaxDynamicSharedMemorySize, SMB);

    dim3 tb(32, 8);
    // weight transposes (rounded to tf32): (K,N) -> (Npad,K)
    transpose_kernel<<<dim3(16, 6),  tb>>>(embed_w, wte, 192, 512, 512);
    transpose_kernel<<<dim3(4, 16),  tb>>>(pw,      wtp, 512, 64, 128);   // zero-padded rows
    for (int l = 0; l < NL_; l++) {
        transpose_kernel<<<dim3(16,16), tb>>>(wq + (size_t)l*D_*D_,   wtq + (size_t)l*D_*D_,   512, 512, 512);
        transpose_kernel<<<dim3(16,16), tb>>>(wk + (size_t)l*D_*D_,   wtk + (size_t)l*D_*D_,   512, 512, 512);
        transpose_kernel<<<dim3(16,16), tb>>>(wv + (size_t)l*D_*D_,   wtv + (size_t)l*D_*D_,   512, 512, 512);
        transpose_kernel<<<dim3(16,16), tb>>>(wo + (size_t)l*D_*D_,   wto + (size_t)l*D_*D_,   512, 512, 512);
        transpose_kernel<<<dim3(64,16), tb>>>(w1 + (size_t)l*D_*DFF_, wt1 + (size_t)l*D_*DFF_, 512, 2048, 2048);
        transpose_kernel<<<dim3(16,64), tb>>>(w2 + (size_t)l*D_*DFF_, wt2 + (size_t)l*D_*DFF_, 2048, 512, 512);
    }

    dim3 g512 (4,  MROWS/128);
    dim3 g2048(16, MROWS/128);
    dim3 g64  (1,  MROWS/128);

    // token embedding
    xcat_kernel<<<(MROWS*192 + 255)/256, 256>>>(x, xc);
    tgemm<0,1><<<g512, 256, SMB>>>(xc, wte, nullptr, h, 192, 512);

    for (int l = 0; l < NL_; l++) {
        tgemm<0,1><<<g512, 256, SMB>>>(h, wtq + (size_t)l*D_*D_, bq + l*D_, q, 512, 512);
        tgemm<0,1><<<g512, 256, SMB>>>(h, wtk + (size_t)l*D_*D_, bk + l*D_, k, 512, 512);
        tgemm<0,1><<<g512, 256, SMB>>>(h, wtv + (size_t)l*D_*D_, bv + l*D_, v, 512, 512);

        corr_fft_kernel <<<dim3(B_, 32), 256>>>(q, k, sp);
        corr_ifft_kernel<<<B_, 256>>>(sp, corr);
        topk_kernel     <<<B_, 256>>>(corr, tcw, dly);
        agg_kernel      <<<MROWS, 128>>>(v, tcw, dly, a);

        tgemm<0,1><<<g512, 256, SMB>>>(a, wto + (size_t)l*D_*D_, bo + l*D_, t, 512, 512);
        decomp_kernel<<<dim3(B_, 8, 8), 256>>>(h, t, h2);

        tgemm<1,1><<<g2048, 256, SMB>>>(h2, wt1 + (size_t)l*D_*DFF_, nullptr, ffn, 512, 2048);
        tgemm<0,1><<<g512,  256, SMB>>>(ffn, wt2 + (size_t)l*D_*DFF_, nullptr, t, 2048, 512);
        decomp_kernel<<<dim3(B_, 8, 8), 256>>>(h2, t, h);
    }

    // final my_Layernorm + time-mean subtraction + projection
    ln_kernel<<<MROWS, 128>>>(h, ln_g, ln_b, q);
    colmean_kernel<<<dim3(B_, 4), 128>>>(q, cm);
    cbias_kernel<<<B_, 64>>>(cm, pw, cb);
    tgemm<0,0><<<g64, 256, SMB>>>(q, wtp, pb, outp, 512, 64);
    sub_kernel<<<(MROWS*64 + 255)/256, 256>>>(outp, cb);
}

// round 10
// speedup vs baseline: 3.6237x; 1.0731x over previous
#include <cuda_runtime.h>
#include <math.h>
#include <stdint.h>

#define B_    32
#define L_    1024
#define CIN_  64
#define D_    512
#define DFF_  2048
#define NL_   3
#define TOPK_ 6
#define MROWS (B_*L_)   /* 32768 */

// ---------------- scratch (device globals; allocation-free) ----------------
__device__ float  g_h  [MROWS*D_];
__device__ float  g_h2 [MROWS*D_];
__device__ float  g_q  [MROWS*D_];
__device__ float  g_k  [MROWS*D_];
__device__ float  g_v  [MROWS*D_];
__device__ float  g_a  [MROWS*D_];
__device__ float  g_t  [MROWS*D_];
__device__ float  g_ffn[MROWS*DFF_];
__device__ float  g_xcat[MROWS*3*CIN_];
__device__ float2 g_Spart[B_*32*L_];
__device__ float  g_corr[B_*L_];
__device__ float  g_tcw [B_*TOPK_];
__device__ int    g_dly [B_*TOPK_];
__device__ float  g_cm  [B_*D_];
__device__ float  g_cb  [B_*CIN_];
// transposed (N,K) weights, rounded to tf32
__device__ float  g_wtq[NL_*D_*D_];
__device__ float  g_wtk[NL_*D_*D_];
__device__ float  g_wtv[NL_*D_*D_];
__device__ float  g_wto[NL_*D_*D_];
__device__ float  g_wt1[NL_*DFF_*D_];   // (2048,512) per layer
__device__ float  g_wt2[NL_*D_*DFF_];   // (512,2048) per layer
__device__ float  g_wte[D_*192];        // (512,192)
__device__ float  g_wtp[128*D_];        // (64,512) padded to 128 rows

// ---------------- helpers ----------------
__device__ __forceinline__ float rtf32(float x) {
    uint32_t b = __float_as_uint(x);
    b = (b + 0x1000u) & 0xffffe000u;      // round-to-nearest tf32, zero low bits
    return __uint_as_float(b);
}
__device__ __forceinline__ float2 cadd(float2 a, float2 b){ return make_float2(a.x+b.x, a.y+b.y); }
__device__ __forceinline__ float2 csub(float2 a, float2 b){ return make_float2(a.x-b.x, a.y-b.y); }
__device__ __forceinline__ float2 cmul(float2 a, float2 b){ return make_float2(a.x*b.x-a.y*b.y, a.x*b.y+a.y*b.x); }
__device__ __forceinline__ float2 cneg(float2 a){ return make_float2(-a.x, -a.y); }

__device__ __forceinline__ uint32_t smem_u32(const void* p){
    uint32_t a;
    asm("{ .reg .u64 t; cvta.to.shared.u64 t, %1; cvt.u32.u64 %0, t; }" : "=r"(a) : "l"(p));
    return a;
}
__device__ __forceinline__ void cp16(uint32_t s, const void* g){
    asm volatile("cp.async.cg.shared.global [%0], [%1], 16;" :: "r"(s), "l"(g));
}
__device__ __forceinline__ void ldsm4(uint32_t* r, uint32_t addr){
    asm volatile("ldmatrix.sync.aligned.m8n8.x4.shared.b16 {%0,%1,%2,%3}, [%4];"
        : "=r"(r[0]),"=r"(r[1]),"=r"(r[2]),"=r"(r[3]) : "r"(addr));
}
#define MMA_TF32(d, a, b0, b1) \
    asm volatile("mma.sync.aligned.m16n8k8.row.col.f32.tf32.tf32.f32 " \
        "{%0,%1,%2,%3},{%4,%5,%6,%7},{%8,%9},{%0,%1,%2,%3};" \
        : "+f"((d)[0]),"+f"((d)[1]),"+f"((d)[2]),"+f"((d)[3]) \
        : "r"((a)[0]),"r"((a)[1]),"r"((a)[2]),"r"((a)[3]), "r"(b0),"r"(b1))

// ---------------- fused weight transposes: one launch, job table ----------------
#define NJOBS 20
struct TJobs {
    const float* src[NJOBS];
    float*       dst[NJOBS];
    int K[NJOBS], N[NJOBS], Npad[NJOBS], tilesX[NJOBS];
    int cum[NJOBS + 1];
};

__global__ void transpose_all_kernel(TJobs jb)
{
    __shared__ float t[32][33];
    int bid = blockIdx.x;
    int m = 0;
    while (bid >= jb.cum[m + 1]) m++;
    int lid = bid - jb.cum[m];
    int tX = jb.tilesX[m];
    int nb = (lid % tX) << 5, kb = (lid / tX) << 5;
    int K = jb.K[m], N = jb.N[m], Npad = jb.Npad[m];
    const float* in = jb.src[m];
    float* out = jb.dst[m];
    int x = threadIdx.x, y = threadIdx.y;     // 32 x 8
#pragma unroll
    for (int i = 0; i < 32; i += 8) {
        int k = kb + y + i, n = nb + x;
        t[y + i][x] = (k < K && n < N) ? in[(size_t)k * N + n] : 0.f;
    }
    __syncthreads();
#pragma unroll
    for (int i = 0; i < 32; i += 8) {
        int n = nb + y + i, k = kb + x;
        if (n < Npad && k < K) out[(size_t)n * K + k] = rtf32(t[x][y + i]);
    }
}

// ---------------- circular-pad gather for token embedding ----------------
__global__ void xcat_kernel(const float* __restrict__ x, float* __restrict__ xc)
{
    int idx = blockIdx.x*blockDim.x + threadIdx.x;
    if (idx >= MROWS*192) return;
    int row = idx / 192, cc = idx % 192;
    int j = cc >> 6, c = cc & 63;
    int b = row >> 10, l = row & 1023;
    int ls = (l + j + 1023) & 1023;
    xc[idx] = rtf32(x[((((size_t)b)<<10) + ls)*64 + c]);
}

// ---------------- tf32 mma.sync GEMM: C[M,N] = A[M,K] * WT[N,K]^T ----------------
// BM=128, BN=128, BK=32; 8 warps of 64x32; 3-stage cp.async pipeline.
template<int GELU, int ROUND>
__global__ __launch_bounds__(256)
void tgemm(const float* __restrict__ A, const float* __restrict__ WT,
           const float* __restrict__ bias, float* __restrict__ C, int K, int N)
{
    constexpr int STG_F = 8192;                 // floats per stage: A 4096 + B 4096
    extern __shared__ float sm[];
    int tid = threadIdx.x;
    int lane = tid & 31, wid = tid >> 5;
    int wm = wid & 1, wn = wid >> 1;            // warp grid 2(m) x 4(n)
    int bx = blockIdx.x, by = blockIdx.y;

    const float* Ab = A  + (size_t)(by * 128) * (size_t)K;
    const float* Bb = WT + (size_t)(bx * 128) * (size_t)K;
    const int nck = K >> 5;

    uint32_t sbase = smem_u32(sm);

    auto load = [&](int ck, int s){
        const float* ap = Ab + ck * 32;
        const float* bp = Bb + ck * 32;
        uint32_t st  = sbase + (uint32_t)s * (STG_F * 4);
        uint32_t st2 = st + 4096 * 4;
#pragma unroll
        for (int i = 0; i < 4; i++) {
            int t = tid + i*256;
            int row = t >> 3, ch = t & 7;
            uint32_t off = (uint32_t)((row << 7) + ((ch ^ (row & 7)) << 4));
            cp16(st + off, ap + (size_t)row*K + (ch << 2));
        }
#pragma unroll
        for (int i = 0; i < 4; i++) {
            int t = tid + i*256;
            int row = t >> 3, ch = t & 7;
            uint32_t off = (uint32_t)((row << 7) + ((ch ^ (row & 7)) << 4));
            cp16(st2 + off, bp + (size_t)row*K + (ch << 2));
        }
        asm volatile("cp.async.commit_group;" ::: "memory");
    };

    float acc[4][4][4];
#pragma unroll
    for (int mt = 0; mt < 4; mt++)
#pragma unroll
        for (int nt = 0; nt < 4; nt++)
#pragma unroll
            for (int j = 0; j < 4; j++) acc[mt][nt][j] = 0.f;

    int g = lane >> 3, r8 = lane & 7;
    int rA[4], rB[2];
#pragma unroll
    for (int mt = 0; mt < 4; mt++) rA[mt] = wm*64 + mt*16 + (g & 1)*8 + r8;
#pragma unroll
    for (int p = 0; p < 2; p++)    rB[p]  = wn*32 + p*16 + (g >> 1)*8 + r8;
    int chA = g >> 1;
    int chB = g & 1;

    load(0, 0); load(1, 1); load(2, 2);
    int s = 0;

    for (int ck = 0; ck < nck; ck++) {
        asm volatile("cp.async.wait_group 2;" ::: "memory");
        __syncthreads();
        uint32_t sa = sbase + (uint32_t)s * (STG_F * 4);
        uint32_t sb = sa + 4096 * 4;
#pragma unroll
        for (int kk = 0; kk < 4; kk++) {
            uint32_t af[4][4], bf[2][4];
#pragma unroll
            for (int mt = 0; mt < 4; mt++) {
                int ch = 2*kk + chA;
                uint32_t off = (uint32_t)((rA[mt] << 7) + ((ch ^ (rA[mt] & 7)) << 4));
                ldsm4(af[mt], sa + off);
            }
#pragma unroll
            for (int p = 0; p < 2; p++) {
                int ch = 2*kk + chB;
                uint32_t off = (uint32_t)((rB[p] << 7) + ((ch ^ (rB[p] & 7)) << 4));
                ldsm4(bf[p], sb + off);
            }
#pragma unroll
            for (int mt = 0; mt < 4; mt++)
#pragma unroll
                for (int nt = 0; nt < 4; nt++) {
                    int p = nt >> 1, q = nt & 1;
                    MMA_TF32(acc[mt][nt], af[mt], bf[p][2*q], bf[p][2*q+1]);
                }
        }
        __syncthreads();
        if (ck + 3 < nck) load(ck + 3, s);
        else asm volatile("cp.async.commit_group;" ::: "memory");
        s = (s == 2) ? 0 : s + 1;
    }

    // epilogue
#pragma unroll
    for (int mt = 0; mt < 4; mt++) {
        int r0 = by*128 + wm*64 + mt*16 + (lane >> 2);
        float* row0 = C + (size_t)r0 * (size_t)N;
        float* row1 = row0 + ((size_t)N << 3);   // r0 + 8
#pragma unroll
        for (int nt = 0; nt < 4; nt++) {
            int c = bx*128 + wn*32 + nt*8 + ((lane & 3) << 1);
            if (c < N) {
                float v0 = acc[mt][nt][0], v1 = acc[mt][nt][1];
                float v2 = acc[mt][nt][2], v3 = acc[mt][nt][3];
                if (bias != nullptr) {
                    float b0c = bias[c], b1c = bias[c+1];
                    v0 += b0c; v1 += b1c; v2 += b0c; v3 += b1c;
                }
                if (GELU) {
                    v0 = 0.5f*v0*(1.f + erff(v0*0.7071067811865475f));
                    v1 = 0.5f*v1*(1.f + erff(v1*0.7071067811865475f));
                    v2 = 0.5f*v2*(1.f + erff(v2*0.7071067811865475f));
                    v3 = 0.5f*v3*(1.f + erff(v3*0.7071067811865475f));
                }
                if (ROUND) { v0 = rtf32(v0); v1 = rtf32(v1); v2 = rtf32(v2); v3 = rtf32(v3); }
                *(float2*)(row0 + c) = make_float2(v0, v1);
                *(float2*)(row1 + c) = make_float2(v2, v3);
            }
        }
    }
}

// ---------------- length-1024 radix-4 FFT (input base-4 digit-reversed) --------
// tw[j] = e^{-2*pi*i*j/1024}, j in [0,512). INV=1: inverse (conjugated twiddles).
template<int INV>
__device__ __forceinline__ float2 twget(const float2* tw, int e)
{
    float2 w = (e < 512) ? tw[e] : cneg(tw[e - 512]);
    if (INV) w.y = -w.y;
    return w;
}

template<int INV>
__device__ void fft1024_r4(float2* z, const float2* tw)
{
    int tid = threadIdx.x;   // blockDim == 256; one radix-4 butterfly per thread per stage
#pragma unroll
    for (int q = 1; q <= 256; q <<= 2) {
        int step = 256 / q;                  // = N/(4q) ... w_size^j = w_N^{j*step}
        int j = tid & (q - 1);
        int base = ((tid & ~(q - 1)) << 2) + j;
        float2 x0 = z[base];
        float2 x1 = cmul(twget<INV>(tw, j*step),        z[base + q]);
        float2 x2 = cmul(twget<INV>(tw, 2*j*step),      z[base + 2*q]);
        float2 x3 = cmul(twget<INV>(tw, 3*j*step),      z[base + 3*q]);
        float2 t0 = cadd(x0, x2), t1 = csub(x0, x2);
        float2 t2 = cadd(x1, x3);
        float2 d  = csub(x1, x3);
        float2 t3 = INV ? make_float2(-d.y, d.x) : make_float2(d.y, -d.x);  // ±i*(x1-x3)
        z[base]       = cadd(t0, t2);
        z[base + q]   = cadd(t1, t3);
        z[base + 2*q] = csub(t0, t2);
        z[base + 3*q] = csub(t1, t3);
        __syncthreads();
    }
}

__device__ __forceinline__ int r4rev(int t)
{
    int r = 0;
#pragma unroll
    for (int i = 0; i < 5; i++) { r = (r << 2) | (t & 3); t >>= 2; }
    return r;
}

__global__ __launch_bounds__(256)
void corr_fft_kernel(const float* __restrict__ q, const float* __restrict__ k,
                     float2* __restrict__ Spart)
{
    __shared__ float2 z[1024];
    __shared__ float2 acc[1024];
    __shared__ float2 tw[512];
    int tid = threadIdx.x;
    int b = blockIdx.x, g = blockIdx.y;

    for (int i = tid; i < 512; i += 256) {
        float s, c;
        sincosf(-6.283185307179586f * (float)i / 1024.f, &s, &c);
        tw[i] = make_float2(c, s);
    }
    for (int i = tid; i < 1024; i += 256) acc[i] = make_float2(0.f, 0.f);
    __syncthreads();

    const float* qb = q + (((size_t)b) << 10) * 512;
    const float* kb = k + (((size_t)b) << 10) * 512;

    for (int dd = 0; dd < 16; dd++) {
        int d = (g << 4) + dd;
        for (int t = tid; t < 1024; t += 256) {
            z[r4rev(t)] = make_float2(qb[(((size_t)t) << 9) + d], kb[(((size_t)t) << 9) + d]);
        }
        __syncthreads();
        fft1024_r4<0>(z, tw);
        for (int f = tid; f < 1024; f += 256) {
            float2 Zf = z[f];
            float2 Zm = z[(1024 - f) & 1023];
            float Qx = 0.5f*(Zf.x + Zm.x), Qy = 0.5f*(Zf.y - Zm.y);
            float Kx = 0.5f*(Zf.y + Zm.y), Ky = 0.5f*(Zm.x - Zf.x);
            float2 P = make_float2(Qx*Kx + Qy*Ky, Qy*Kx - Qx*Ky);
            acc[f] = cadd(acc[f], P);
        }
        __syncthreads();
    }
    float2* outp = Spart + ((((size_t)b) << 5) + g) * 1024;
    for (int f = tid; f < 1024; f += 256) outp[f] = acc[f];
}

__global__ __launch_bounds__(256)
void corr_ifft_kernel(const float2* __restrict__ Spart, float* __restrict__ corr)
{
    __shared__ float2 z[1024];
    __shared__ float2 tw[512];
    int tid = threadIdx.x;
    int b = blockIdx.x;

    for (int i = tid; i < 512; i += 256) {
        float s, c;
        sincosf(-6.283185307179586f * (float)i / 1024.f, &s, &c);
        tw[i] = make_float2(c, s);
    }
    __syncthreads();
    for (int t = tid; t < 1024; t += 256) {
        float2 s = make_float2(0.f, 0.f);
        const float2* sp = Spart + ((((size_t)b) << 5) * 1024) + t;
        for (int g2 = 0; g2 < 32; g2++) s = cadd(s, sp[(size_t)g2 << 10]);
        z[r4rev(t)] = s;
    }
    __syncthreads();
    fft1024_r4<1>(z, tw);
    const float scale = 1.f / (1024.f * 512.f);
    for (int t = tid; t < 1024; t += 256)
        corr[(b << 10) + t] = z[t].x * scale;
}

__global__ __launch_bounds__(256)
void topk_kernel(const float* __restrict__ corr, float* __restrict__ tcw, int* __restrict__ dly)
{
    int b = blockIdx.x, t = threadIdx.x;
    __shared__ float vals[1024];
    __shared__ float rv[256];
    __shared__ int   ri[256];
    __shared__ float wv[TOPK_];
    __shared__ int   wi[TOPK_];
    for (int i = t; i < 1024; i += 256) vals[i] = corr[(b << 10) + i];
    __syncthreads();
    for (int kk = 0; kk < TOPK_; kk++) {
        float bm = -INFINITY; int bi = 0x7fffffff;
        for (int i = t; i < 1024; i += 256) {
            float v = vals[i];
            if (v > bm || (v == bm && i < bi)) { bm = v; bi = i; }
        }
        rv[t] = bm; ri[t] = bi;
        __syncthreads();
        for (int s = 128; s > 0; s >>= 1) {
            if (t < s) {
                if (rv[t+s] > rv[t] || (rv[t+s] == rv[t] && ri[t+s] < ri[t])) {
                    rv[t] = rv[t+s]; ri[t] = ri[t+s];
                }
            }
            __syncthreads();
        }
        if (t == 0) { wv[kk] = rv[0]; wi[kk] = ri[0]; vals[ri[0]] = -INFINITY; }
        __syncthreads();
    }
    if (t == 0) {
        float m = wv[0];
        for (int kk = 1; kk < TOPK_; kk++) m = fmaxf(m, wv[kk]);
        float e[TOPK_], s = 0.f;
        for (int kk = 0; kk < TOPK_; kk++) { e[kk] = expf(wv[kk] - m); s += e[kk]; }
        float inv = 1.f / s;
        for (int kk = 0; kk < TOPK_; kk++) {
            tcw[b*TOPK_ + kk] = e[kk] * inv;
            dly[b*TOPK_ + kk] = wi[kk];
        }
    }
}

__global__ __launch_bounds__(128)
void agg_kernel(const float* __restrict__ v, const float* __restrict__ tcw,
                const int* __restrict__ dly, float* __restrict__ outp)
{
    int bl = blockIdx.x;
    int b = bl >> 10, l = bl & 1023;
    __shared__ float w[TOPK_];
    __shared__ int   dd[TOPK_];
    if (threadIdx.x < TOPK_) {
        w[threadIdx.x]  = tcw[b*TOPK_ + threadIdx.x];
        dd[threadIdx.x] = dly[b*TOPK_ + threadIdx.x];
    }
    __syncthreads();
    int c = threadIdx.x << 2;
    float4 acc = make_float4(0.f, 0.f, 0.f, 0.f);
#pragma unroll
    for (int kk = 0; kk < TOPK_; kk++) {
        int row = (l + dd[kk]) & 1023;
        float4 vv = *(const float4*)(v + (((((size_t)b) << 10) + row) << 9) + c);
        acc.x = fmaf(w[kk], vv.x, acc.x);
        acc.y = fmaf(w[kk], vv.y, acc.y);
        acc.z = fmaf(w[kk], vv.z, acc.z);
        acc.w = fmaf(w[kk], vv.w, acc.w);
    }
    acc.x = rtf32(acc.x); acc.y = rtf32(acc.y); acc.z = rtf32(acc.z); acc.w = rtf32(acc.w);
    *(float4*)(outp + (((size_t)bl) << 9) + c) = acc;
}

__global__ __launch_bounds__(256)
void decomp_kernel(const float* __restrict__ in1, const float* __restrict__ in2,
                   float* __restrict__ outp)
{
    __shared__ float s[152][64];
    int b = blockIdx.x, lt = blockIdx.y, dt = blockIdx.z;
    int l0 = lt << 7, d0 = dt << 6;
    int tid = threadIdx.x;
    for (int i = tid; i < 152*64; i += 256) {
        int r = i >> 6, d = i & 63;
        int l = l0 - 12 + r;
        l = l < 0 ? 0 : (l > 1023 ? 1023 : l);
        size_t gi = (((((size_t)b) << 10) + l) << 9) + d0 + d;
        s[r][d] = in1[gi] + in2[gi];
    }
    __syncthreads();
    int d = tid & 63, ch = tid >> 6;
    int lb = ch << 5;
    float sum = 0.f;
#pragma unroll
    for (int j = 0; j < 25; j++) sum += s[lb + j][d];
    for (int i = 0; i < 32; i++) {
        size_t gi = (((((size_t)b) << 10) + (l0 + lb + i)) << 9) + d0 + d;
        outp[gi] = rtf32(s[lb + 12 + i][d] - sum * (1.f/25.f));
        if (i != 31) sum += s[lb + 25 + i][d] - s[lb + i][d];
    }
}

__global__ __launch_bounds__(128)
void ln_kernel(const float* __restrict__ h, const float* __restrict__ gam,
               const float* __restrict__ bet, float* __restrict__ hn)
{
    int row = blockIdx.x;
    int t = threadIdx.x;
    const float4 x = *(const float4*)(h + (((size_t)row) << 9) + (t << 2));
    float s1 = x.x + x.y + x.z + x.w;
    float s2 = x.x*x.x + x.y*x.y + x.z*x.z + x.w*x.w;
#pragma unroll
    for (int o = 16; o > 0; o >>= 1) {
        s1 += __shfl_xor_sync(0xffffffffu, s1, o);
        s2 += __shfl_xor_sync(0xffffffffu, s2, o);
    }
    __shared__ float a1[4], a2[4];
    if ((t & 31) == 0) { a1[t >> 5] = s1; a2[t >> 5] = s2; }
    __syncthreads();
    s1 = a1[0] + a1[1] + a1[2] + a1[3];
    s2 = a2[0] + a2[1] + a2[2] + a2[3];
    float mu  = s1 * (1.f/512.f);
    float var = s2 * (1.f/512.f) - mu*mu;
    float rs  = rsqrtf(var + 1e-5f);
    int c = t << 2;
    float4 o4;
    o4.x = rtf32((x.x - mu)*rs*gam[c+0] + bet[c+0]);
    o4.y = rtf32((x.y - mu)*rs*gam[c+1] + bet[c+1]);
    o4.z = rtf32((x.z - mu)*rs*gam[c+2] + bet[c+2]);
    o4.w = rtf32((x.w - mu)*rs*gam[c+3] + bet[c+3]);
    *(float4*)(hn + (((size_t)row) << 9) + c) = o4;
}

__global__ __launch_bounds__(128)
void colmean_kernel(const float* __restrict__ hn, float* __restrict__ cm)
{
    int b = blockIdx.x;
    int d = blockIdx.y * 128 + threadIdx.x;
    float s = 0.f;
    const float* p = hn + ((((size_t)b) << 10) << 9) + d;
    for (int l = 0; l < 1024; l++) s += p[((size_t)l) << 9];
    cm[(b << 9) + d] = s * (1.f/1024.f);
}

__global__ __launch_bounds__(64)
void cbias_kernel(const float* __restrict__ cm, const float* __restrict__ pw,
                  float* __restrict__ cb)
{
    int b = blockIdx.x, n = threadIdx.x;
    float s = 0.f;
    for (int d2 = 0; d2 < 512; d2++) s = fmaf(cm[(b << 9) + d2], rtf32(pw[d2*64 + n]), s);
    cb[(b << 6) + n] = s;
}

__global__ void sub_kernel(float* __restrict__ outp, const float* __restrict__ cb)
{
    int i = blockIdx.x * blockDim.x + threadIdx.x;
    if (i >= MROWS*64) return;
    outp[i] -= cb[((i >> 16) << 6) + (i & 63)];
}

// ---------------- host launcher ----------------
extern "C" void kernel_launch(void* const* d_in, const int* in_sizes, int n_in,
                              void* d_out, int out_size)
{
    const float* x       = (const float*)d_in[0];
    const float* embed_w = (const float*)d_in[1];
    const float* wq = (const float*)d_in[2];  const float* bq = (const float*)d_in[3];
    const float* wk = (const float*)d_in[4];  const float* bk = (const float*)d_in[5];
    const float* wv = (const float*)d_in[6];  const float* bv = (const float*)d_in[7];
    const float* wo = (const float*)d_in[8];  const float* bo = (const float*)d_in[9];
    const float* w1 = (const float*)d_in[10]; const float* w2 = (const float*)d_in[11];
    const float* ln_g = (const float*)d_in[12]; const float* ln_b = (const float*)d_in[13];
    const float* pw = (const float*)d_in[14]; const float* pb = (const float*)d_in[15];
    float* outp = (float*)d_out;
    (void)in_sizes; (void)n_in; (void)out_size;

    float *h, *h2, *q, *k, *v, *a, *t, *ffn, *xc, *corr, *tcw, *cm, *cb;
    float *wtq, *wtk, *wtv, *wto, *wt1, *wt2, *wte, *wtp;
    float2* sp; int* dly;
    cudaGetSymbolAddress((void**)&h,   g_h);
    cudaGetSymbolAddress((void**)&h2,  g_h2);
    cudaGetSymbolAddress((void**)&q,   g_q);
    cudaGetSymbolAddress((void**)&k,   g_k);
    cudaGetSymbolAddress((void**)&v,   g_v);
    cudaGetSymbolAddress((void**)&a,   g_a);
    cudaGetSymbolAddress((void**)&t,   g_t);
    cudaGetSymbolAddress((void**)&ffn, g_ffn);
    cudaGetSymbolAddress((void**)&xc,  g_xcat);
    cudaGetSymbolAddress((void**)&sp,  g_Spart);
    cudaGetSymbolAddress((void**)&corr,g_corr);
    cudaGetSymbolAddress((void**)&tcw, g_tcw);
    cudaGetSymbolAddress((void**)&dly, g_dly);
    cudaGetSymbolAddress((void**)&cm,  g_cm);
    cudaGetSymbolAddress((void**)&cb,  g_cb);
    cudaGetSymbolAddress((void**)&wtq, g_wtq);
    cudaGetSymbolAddress((void**)&wtk, g_wtk);
    cudaGetSymbolAddress((void**)&wtv, g_wtv);
    cudaGetSymbolAddress((void**)&wto, g_wto);
    cudaGetSymbolAddress((void**)&wt1, g_wt1);
    cudaGetSymbolAddress((void**)&wt2, g_wt2);
    cudaGetSymbolAddress((void**)&wte, g_wte);
    cudaGetSymbolAddress((void**)&wtp, g_wtp);

    const int SMB = 3 * 8192 * 4;   // 98304 bytes
    cudaFuncSetAttribute(tgemm<0,1>, cudaFuncAttributeMaxDynamicSharedMemorySize, SMB);
    cudaFuncSetAttribute(tgemm<1,1>, cudaFuncAttributeMaxDynamicSharedMemorySize, SMB);
    cudaFuncSetAttribute(tgemm<0,0>, cudaFuncAttributeMaxDynamicSharedMemorySize, SMB);

    // ---- build fused transpose job table (one launch for all 20 weights) ----
    TJobs jb;
    int nj = 0, cum = 0;
    auto addjob = [&](const float* src, float* dst, int K, int N, int Npad) {
        jb.src[nj] = src; jb.dst[nj] = dst;
        jb.K[nj] = K; jb.N[nj] = N; jb.Npad[nj] = Npad;
        int tx = (Npad + 31) / 32, ty = (K + 31) / 32;
        jb.tilesX[nj] = tx;
        jb.cum[nj] = cum;
        cum += tx * ty;
        nj++;
    };
    addjob(embed_w, wte, 192, 512, 512);
    addjob(pw,      wtp, 512, 64, 128);
    for (int l = 0; l < NL_; l++) {
        addjob(wq + (size_t)l*D_*D_,   wtq + (size_t)l*D_*D_,   512, 512, 512);
        addjob(wk + (size_t)l*D_*D_,   wtk + (size_t)l*D_*D_,   512, 512, 512);
        addjob(wv + (size_t)l*D_*D_,   wtv + (size_t)l*D_*D_,   512, 512, 512);
        addjob(wo + (size_t)l*D_*D_,   wto + (size_t)l*D_*D_,   512, 512, 512);
        addjob(w1 + (size_t)l*D_*DFF_, wt1 + (size_t)l*D_*DFF_, 512, 2048, 2048);
        addjob(w2 + (size_t)l*D_*DFF_, wt2 + (size_t)l*D_*DFF_, 2048, 512, 512);
    }
    jb.cum[nj] = cum;
    transpose_all_kernel<<<cum, dim3(32, 8)>>>(jb);

    dim3 g512 (4,  MROWS/128);
    dim3 g2048(16, MROWS/128);
    dim3 g64  (1,  MROWS/128);

    // token embedding
    xcat_kernel<<<(MROWS*192 + 255)/256, 256>>>(x, xc);
    tgemm<0,1><<<g512, 256, SMB>>>(xc, wte, nullptr, h, 192, 512);

    for (int l = 0; l < NL_; l++) {
        tgemm<0,1><<<g512, 256, SMB>>>(h, wtq + (size_t)l*D_*D_, bq + l*D_, q, 512, 512);
        tgemm<0,1><<<g512, 256, SMB>>>(h, wtk + (size_t)l*D_*D_, bk + l*D_, k, 512, 512);
        tgemm<0,1><<<g512, 256, SMB>>>(h, wtv + (size_t)l*D_*D_, bv + l*D_, v, 512, 512);

        corr_fft_kernel <<<dim3(B_, 32), 256>>>(q, k, sp);
        corr_ifft_kernel<<<B_, 256>>>(sp, corr);
        topk_kernel     <<<B_, 256>>>(corr, tcw, dly);
        agg_kernel      <<<MROWS, 128>>>(v, tcw, dly, a);

        tgemm<0,1><<<g512, 256, SMB>>>(a, wto + (size_t)l*D_*D_, bo + l*D_, t, 512, 512);
        decomp_kernel<<<dim3(B_, 8, 8), 256>>>(h, t, h2);

        tgemm<1,1><<<g2048, 256, SMB>>>(h2, wt1 + (size_t)l*D_*DFF_, nullptr, ffn, 512, 2048);
        tgemm<0,1><<<g512,  256, SMB>>>(ffn, wt2 + (size_t)l*D_*DFF_, nullptr, t, 2048, 512);
        decomp_kernel<<<dim3(B_, 8, 8), 256>>>(h2, t, h);
    }

    // final my_Layernorm + time-mean subtraction + projection
    ln_kernel<<<MROWS, 128>>>(h, ln_g, ln_b, q);
    colmean_kernel<<<dim3(B_, 4), 128>>>(q, cm);
    cbias_kernel<<<B_, 64>>>(cm, pw, cb);
    tgemm<0,0><<<g64, 256, SMB>>>(q, wtp, pb, outp, 512, 64);
    sub_kernel<<<(MROWS*64 + 255)/256, 256>>>(outp, cb);
}